// round 6
// baseline (speedup 1.0000x reference)
#include <cuda_runtime.h>
#include <cuda_fp16.h>

#define NN 100000
#define EE 800000
#define SCAN_BLKS ((NN + 1023) / 1024)   // 98

// ---------------- scratch (__device__ globals: no allocation allowed) ----------------
__device__ __align__(16) __half g_h[(size_t)NN * 256];   // [N][H*64] transformed feats (fp16)
__device__ __align__(16) __half g_xh[(size_t)NN * 64];   // fp16 copy of x
__device__ __align__(16) __half g_g1h[(size_t)NN * 64];  // hop-1 aggregate (fp16)
__device__ float g_local[(size_t)NN * 64];   // attention output (head-mean)
__device__ float g_g2[(size_t)NN * 64];      // hop-2 aggregate
__device__ __align__(16) float g_ssrc[NN * 4];           // per-node src logits [N][H]
__device__ __align__(16) float g_sdst[NN * 4];           // per-node dst logits [N][H]
__device__ int   g_deg[NN];
__device__ int   g_offs[NN + 1];
__device__ int   g_cursor[NN];
__device__ int   g_csr[EE];                  // src node per CSR slot (sorted by dst)
__device__ float g_W2[64 * 64];              // W_g @ W_w[64:128]
__device__ float g_b2[64];                   // b_g @ W_w[64:128] + b_w
__device__ int   g_is64;                     // edge_index dtype flag
__device__ int   g_bsum[SCAN_BLKS];
__device__ int   g_bbase[SCAN_BLKS];

__device__ __forceinline__ float lrelu(float v) { return v > 0.f ? v : 0.2f * v; }

// ---------------- -1: detect edge_index dtype (int32 vs int64) ----------------
__global__ void k_detect(const unsigned int* __restrict__ w) {
    __shared__ int allzero;
    if (threadIdx.x == 0) allzero = 1;
    __syncthreads();
    for (int i = threadIdx.x; i < 1024; i += blockDim.x)
        if (w[2 * i + 1] != 0u) allzero = 0;
    __syncthreads();
    if (threadIdx.x == 0) g_is64 = allzero;
}

__device__ __forceinline__ int edge_at(const void* ei, int idx) {
    if (g_is64) return (int)((const long long*)ei)[idx];
    return ((const int*)ei)[idx];
}

// ---------------- 0: zero scratch + fp16 copy of x ----------------
__global__ void k_init(const float* __restrict__ x) {
    int i = blockIdx.x * blockDim.x + threadIdx.x;
    int st = gridDim.x * blockDim.x;
    for (int j = i; j < NN; j += st) g_deg[j] = 0;
    for (int j = i; j < NN * 4; j += st) { g_ssrc[j] = 0.f; g_sdst[j] = 0.f; }
    const float2* x2 = (const float2*)x;
    __half2* xh2 = (__half2*)g_xh;
    for (int j = i; j < NN * 32; j += st) {
        float2 v = x2[j];
        xh2[j] = __floats2half2_rn(v.x, v.y);
    }
}

// ---------------- 1: degree histogram ----------------
__global__ void k_hist(const void* __restrict__ ei) {
    int i = blockIdx.x * blockDim.x + threadIdx.x;
    int st = gridDim.x * blockDim.x;
    for (int e = i; e < EE; e += st) {
        int d = edge_at(ei, EE + e);
        atomicAdd(&g_deg[d], 1);
    }
}

// ---------------- 2: device-wide exclusive scan of g_deg (3 phases) ----------------
__global__ void __launch_bounds__(1024) k_scan_a() {
    __shared__ int sm[1024];
    int tid = threadIdx.x;
    int gid = blockIdx.x * 1024 + tid;
    int v = (gid < NN) ? g_deg[gid] : 0;
    sm[tid] = v;
    __syncthreads();
#pragma unroll
    for (int off = 1; off < 1024; off <<= 1) {
        int t = (tid >= off) ? sm[tid - off] : 0;
        __syncthreads();
        sm[tid] += t;
        __syncthreads();
    }
    if (gid < NN) g_offs[gid] = sm[tid] - v;
    if (tid == 1023) g_bsum[blockIdx.x] = sm[1023];
}

__global__ void __launch_bounds__(128) k_scan_b() {
    __shared__ int sm[128];
    int tid = threadIdx.x;
    int v = (tid < SCAN_BLKS) ? g_bsum[tid] : 0;
    sm[tid] = v;
    __syncthreads();
#pragma unroll
    for (int off = 1; off < 128; off <<= 1) {
        int t = (tid >= off) ? sm[tid - off] : 0;
        __syncthreads();
        sm[tid] += t;
        __syncthreads();
    }
    if (tid < SCAN_BLKS) g_bbase[tid] = sm[tid] - v;
    if (tid == 127) g_offs[NN] = sm[127];
}

__global__ void __launch_bounds__(1024) k_scan_c() {
    int gid = blockIdx.x * 1024 + threadIdx.x;
    if (gid < NN) {
        int o = g_offs[gid] + g_bbase[blockIdx.x];
        g_offs[gid] = o;
        g_cursor[gid] = o;
    }
}

// ---------------- 3: scatter edges into CSR by dst ----------------
__global__ void k_scatter(const void* __restrict__ ei) {
    int i = blockIdx.x * blockDim.x + threadIdx.x;
    int st = gridDim.x * blockDim.x;
    for (int e = i; e < EE; e += st) {
        int s = edge_at(ei, e);
        int d = edge_at(ei, EE + e);
        int pos = atomicAdd(&g_cursor[d], 1);
        g_csr[pos] = s;
    }
}

// ---------------- 4: h = x @ W_att (fp32 math, fp16 store) + logits ----------------
#define FEAT_NPB 64
#define FEAT_BATCH 8
__global__ void __launch_bounds__(128) k_feat(const float* __restrict__ x,
                                              const float* __restrict__ W_att,
                                              const float* __restrict__ a_src,
                                              const float* __restrict__ a_dst) {
    __shared__ float xsh[FEAT_BATCH][64];
    int tid = threadIdx.x;
    int lane = tid & 31;
    int node0 = blockIdx.x * FEAT_NPB;

    for (int hp = 0; hp < 2; hp++) {
        int hh = hp * 2 + (tid >> 6);
        int o = tid & 63;
        float wcol[64];
        const float* wp = W_att + (size_t)hh * 64 * 64 + o;
#pragma unroll
        for (int k = 0; k < 64; k++) wcol[k] = wp[k * 64];
        float av_s = a_src[hh * 64 + o];
        float av_d = a_dst[hh * 64 + o];

        for (int nb = 0; nb < FEAT_NPB; nb += FEAT_BATCH) {
            __syncthreads();
            for (int i = tid; i < FEAT_BATCH * 64; i += 128) {
                int nn = node0 + nb + (i >> 6);
                xsh[i >> 6][i & 63] = (nn < NN) ? x[(size_t)nn * 64 + (i & 63)] : 0.f;
            }
            __syncthreads();
#pragma unroll 1
            for (int bb = 0; bb < FEAT_BATCH; bb++) {
                int n = node0 + nb + bb;
                if (n >= NN) break;
                const float4* xr = (const float4*)xsh[bb];
                float acc = 0.f;
#pragma unroll
                for (int kk = 0; kk < 16; kk++) {
                    float4 xv = xr[kk];
                    acc += xv.x * wcol[kk * 4 + 0];
                    acc += xv.y * wcol[kk * 4 + 1];
                    acc += xv.z * wcol[kk * 4 + 2];
                    acc += xv.w * wcol[kk * 4 + 3];
                }
                g_h[(size_t)n * 256 + hp * 128 + tid] = __float2half_rn(acc);
                float vs = acc * av_s;
                float vd = acc * av_d;
#pragma unroll
                for (int off = 16; off; off >>= 1) {
                    vs += __shfl_xor_sync(0xFFFFFFFFu, vs, off);
                    vd += __shfl_xor_sync(0xFFFFFFFFu, vd, off);
                }
                if (lane == 0) {
                    atomicAdd(&g_ssrc[n * 4 + hh], vs);
                    atomicAdd(&g_sdst[n * 4 + hh], vd);
                }
            }
        }
    }
}

// ---------------- 5: attention + hop-1, fused, warp per destination node ----------------
// Softmax without max subtraction (logits ~N(0,2), |max| << 80 -> exp safe in fp32;
// softmax is shift-invariant so the result matches the reference).
// Chunked exp dedup: 8 edges/chunk, lane (4*e + h) computes ONE exp; weights and
// src ids broadcast to consumers via shuffles. 32x fewer MUFU ops than R5.
__global__ void __launch_bounds__(256) k_attn() {
    int gw = (blockIdx.x * blockDim.x + threadIdx.x) >> 5;
    int lane = threadIdx.x & 31;
    if (gw >= NN) return;
    int n = gw;
    int beg = g_offs[n], end = g_offs[n + 1];
    float4 sd = *(const float4*)&g_sdst[n * 4];

    int hsel = lane >> 3;        // consumer head (for h-row columns I own)
    int hw   = lane & 3;         // producer head (for weight I compute)
    float sdh = hw == 0 ? sd.x : hw == 1 ? sd.y : hw == 2 ? sd.z : sd.w;

    float ha[8];
#pragma unroll
    for (int i = 0; i < 8; i++) ha[i] = 0.f;
    float dpart = 0.f;           // partial denominator for head hw
    float xa0 = 0.f, xa1 = 0.f;  // hop-1 partials

    for (int j0 = beg; j0 < end; j0 += 8) {
        int myj = j0 + (lane >> 2);
        int s_my = 0;
        float w = 0.f;
        if (myj < end) {
            s_my = g_csr[myj];
            float ss = g_ssrc[s_my * 4 + hw];
            w = __expf(lrelu(ss + sdh));
        }
        dpart += w;
        int lim = min(8, end - j0);
#pragma unroll 1
        for (int k = 0; k < lim; k++) {
            int   s    = __shfl_sync(0xFFFFFFFFu, s_my, k * 4);
            float wsel = __shfl_sync(0xFFFFFFFFu, w, (k << 2) + hsel);
            const uint4* hr = (const uint4*)(g_h + (size_t)s * 256);
            uint4 hv = hr[lane];
            float2 f0 = __half22float2(*(const __half2*)&hv.x);
            float2 f1 = __half22float2(*(const __half2*)&hv.y);
            float2 f2 = __half22float2(*(const __half2*)&hv.z);
            float2 f3 = __half22float2(*(const __half2*)&hv.w);
            ha[0] += wsel * f0.x; ha[1] += wsel * f0.y;
            ha[2] += wsel * f1.x; ha[3] += wsel * f1.y;
            ha[4] += wsel * f2.x; ha[5] += wsel * f2.y;
            ha[6] += wsel * f3.x; ha[7] += wsel * f3.y;
            unsigned int xv = ((const unsigned int*)(g_xh + (size_t)s * 64))[lane];
            float2 xf = __half22float2(*(const __half2*)&xv);
            xa0 += xf.x; xa1 += xf.y;
        }
    }

    // reduce dpart over lanes with the same hw (bits 2,3,4): all lanes end with den[hw]
    dpart += __shfl_xor_sync(0xFFFFFFFFu, dpart, 4);
    dpart += __shfl_xor_sync(0xFFFFFFFFu, dpart, 8);
    dpart += __shfl_xor_sync(0xFFFFFFFFu, dpart, 16);
    // my head's denominator lives on lane hsel (hsel<4 -> lane&3 == hsel)
    float densel = __shfl_sync(0xFFFFFFFFu, dpart, hsel);
    float isel = 1.f / fmaxf(densel, 1e-16f);

    // normalize my head, then mean over heads (lanes differing in bits 3,4)
#pragma unroll
    for (int i = 0; i < 8; i++) {
        float v = ha[i] * isel;
        v += __shfl_xor_sync(0xFFFFFFFFu, v, 8);
        v += __shfl_xor_sync(0xFFFFFFFFu, v, 16);
        ha[i] = 0.25f * v;
    }
    if (lane < 8) {
        float4* dst = (float4*)(g_local + (size_t)n * 64 + 8 * lane);
        dst[0] = make_float4(ha[0], ha[1], ha[2], ha[3]);
        dst[1] = make_float4(ha[4], ha[5], ha[6], ha[7]);
    }
    float invd = 1.f / fmaxf((float)(end - beg), 1.f);
    __half2* g1 = (__half2*)(g_g1h + (size_t)n * 64);
    g1[lane] = __floats2half2_rn(xa0 * invd, xa1 * invd);
}

// ---------------- 6: hop-2 (fp16 gather, fp32 out) ----------------
__global__ void __launch_bounds__(256) k_glob2() {
    int gw = (blockIdx.x * blockDim.x + threadIdx.x) >> 5;
    int lane = threadIdx.x & 31;
    if (gw >= NN) return;
    int n = gw;
    int beg = g_offs[n], end = g_offs[n + 1];
    float a0 = 0.f, a1 = 0.f;
    for (int j = beg; j < end; j++) {
        int s = g_csr[j];
        const unsigned int* r = (const unsigned int*)(g_g1h + (size_t)s * 64);
        unsigned int v = r[lane];
        float2 f = __half22float2(*(const __half2*)&v);
        a0 += f.x; a1 += f.y;
    }
    float inv = 1.f / fmaxf((float)(end - beg), 1.f);
    float2* dst = (float2*)(g_g2 + (size_t)n * 64 + 2 * lane);
    *dst = make_float2(a0 * inv, a1 * inv);
}

// ---------------- 7: fold W_g into W_w lower half ----------------
__global__ void k_wg(const float* __restrict__ W_g, const float* __restrict__ b_g,
                     const float* __restrict__ W_w, const float* __restrict__ b_w) {
    int i0 = blockIdx.x * blockDim.x + threadIdx.x;
    int st = gridDim.x * blockDim.x;
    for (int idx = i0; idx < 4096; idx += st) {
        int i = idx >> 6, o = idx & 63;
        float s = 0.f;
        for (int k = 0; k < 64; k++)
            s += W_g[i * 64 + k] * W_w[(64 + k) * 64 + o];
        g_W2[idx] = s;
    }
    for (int o = i0; o < 64; o += st) {
        float s = b_w[o];
        for (int k = 0; k < 64; k++)
            s += b_g[k] * W_w[(64 + k) * 64 + o];
        g_b2[o] = s;
    }
}

// ---------------- 8: final projection out = local@W1 + g2@W2 + b2 ----------------
#define FIN_NPB 64
__global__ void __launch_bounds__(256) k_final(const float* __restrict__ W_w,
                                               float* __restrict__ out) {
    __shared__ float W1s[4096];
    __shared__ float W2s[4096];
    __shared__ float bs[64];
    __shared__ float ls[4][64];
    __shared__ float gs[4][64];
    int tid = threadIdx.x;
    for (int i = tid; i < 4096; i += 256) {
        W1s[i] = W_w[i];
        W2s[i] = g_W2[i];
    }
    if (tid < 64) bs[tid] = g_b2[tid];
    __syncthreads();

    int node0 = blockIdx.x * FIN_NPB;
    for (int nb = 0; nb < FIN_NPB; nb += 4) {
        __syncthreads();
        {
            int nn = node0 + nb + (tid >> 6);
            int c = tid & 63;
            if (nn < NN) {
                ls[tid >> 6][c] = g_local[(size_t)nn * 64 + c];
                gs[tid >> 6][c] = g_g2[(size_t)nn * 64 + c];
            }
        }
        __syncthreads();
        int nn = node0 + nb + (tid >> 6);
        if (nn < NN) {
            int o = tid & 63;
            float acc = bs[o];
            const float4* lr = (const float4*)ls[tid >> 6];
            const float4* gr = (const float4*)gs[tid >> 6];
#pragma unroll
            for (int kk = 0; kk < 16; kk++) {
                float4 lv = lr[kk];
                float4 gv = gr[kk];
                acc += lv.x * W1s[(kk * 4 + 0) * 64 + o] + gv.x * W2s[(kk * 4 + 0) * 64 + o];
                acc += lv.y * W1s[(kk * 4 + 1) * 64 + o] + gv.y * W2s[(kk * 4 + 1) * 64 + o];
                acc += lv.z * W1s[(kk * 4 + 2) * 64 + o] + gv.z * W2s[(kk * 4 + 2) * 64 + o];
                acc += lv.w * W1s[(kk * 4 + 3) * 64 + o] + gv.w * W2s[(kk * 4 + 3) * 64 + o];
            }
            out[(size_t)nn * 64 + o] = acc;
        }
    }
}

// ---------------- launch ----------------
extern "C" void kernel_launch(void* const* d_in, const int* in_sizes, int n_in,
                              void* d_out, int out_size) {
    const float* x     = (const float*)d_in[0];
    const void*  ei    = d_in[1];
    const float* W_att = (const float*)d_in[2];
    const float* a_src = (const float*)d_in[3];
    const float* a_dst = (const float*)d_in[4];
    const float* W_g   = (const float*)d_in[5];
    const float* b_g   = (const float*)d_in[6];
    const float* W_w   = (const float*)d_in[7];
    const float* b_w   = (const float*)d_in[8];
    float* out = (float*)d_out;

    k_detect<<<1, 256>>>((const unsigned int*)ei);
    k_init<<<256, 256>>>(x);
    k_hist<<<3125, 256>>>(ei);
    k_scan_a<<<SCAN_BLKS, 1024>>>();
    k_scan_b<<<1, 128>>>();
    k_scan_c<<<SCAN_BLKS, 1024>>>();
    k_scatter<<<3125, 256>>>(ei);
    k_feat<<<(NN + FEAT_NPB - 1) / FEAT_NPB, 128>>>(x, W_att, a_src, a_dst);
    k_attn<<<(NN * 32 + 255) / 256, 256>>>();
    k_glob2<<<(NN * 32 + 255) / 256, 256>>>();
    k_wg<<<17, 256>>>(W_g, b_g, W_w, b_w);
    k_final<<<(NN + FIN_NPB - 1) / FIN_NPB, 256>>>(W_w, out);
}

// round 7
// speedup vs baseline: 1.4755x; 1.4755x over previous
#include <cuda_runtime.h>
#include <cuda_fp16.h>

#define NN 100000
#define EE 800000
#define SCAN_BLKS ((NN + 1023) / 1024)   // 98

// ---------------- scratch (__device__ globals: no allocation allowed) ----------------
__device__ __align__(16) __half g_h[(size_t)NN * 256];   // [N][H*64] transformed feats (fp16)
__device__ __align__(16) __half g_xh[(size_t)NN * 64];   // fp16 copy of x
__device__ __align__(16) __half g_g1h[(size_t)NN * 64];  // hop-1 aggregate (fp16)
__device__ float g_local[(size_t)NN * 64];   // attention output (head-mean)
__device__ float g_g2[(size_t)NN * 64];      // hop-2 aggregate
__device__ __align__(16) float g_ssrc[NN * 4];           // per-node src logits [N][H]
__device__ __align__(16) float g_sdst[NN * 4];           // per-node dst logits [N][H]
__device__ int   g_deg[NN];
__device__ int   g_offs[NN + 1];
__device__ int   g_cursor[NN];
__device__ int   g_csr[EE];                  // src node per CSR slot (sorted by dst)
__device__ float g_W2[64 * 64];              // W_g @ W_w[64:128]
__device__ float g_b2[64];                   // b_g @ W_w[64:128] + b_w
__device__ int   g_is64;                     // edge_index dtype flag
__device__ int   g_bsum[SCAN_BLKS];
__device__ int   g_bbase[SCAN_BLKS];

__device__ __forceinline__ float lrelu(float v) { return v > 0.f ? v : 0.2f * v; }

// ---------------- -1: detect edge_index dtype (int32 vs int64) ----------------
__global__ void k_detect(const unsigned int* __restrict__ w) {
    __shared__ int allzero;
    if (threadIdx.x == 0) allzero = 1;
    __syncthreads();
    for (int i = threadIdx.x; i < 1024; i += blockDim.x)
        if (w[2 * i + 1] != 0u) allzero = 0;
    __syncthreads();
    if (threadIdx.x == 0) g_is64 = allzero;
}

__device__ __forceinline__ int edge_at(const void* ei, int idx) {
    if (g_is64) return (int)((const long long*)ei)[idx];
    return ((const int*)ei)[idx];
}

// ---------------- 0: zero scratch + fp16 copy of x ----------------
__global__ void k_init(const float* __restrict__ x) {
    int i = blockIdx.x * blockDim.x + threadIdx.x;
    int st = gridDim.x * blockDim.x;
    for (int j = i; j < NN; j += st) g_deg[j] = 0;
    for (int j = i; j < NN * 4; j += st) { g_ssrc[j] = 0.f; g_sdst[j] = 0.f; }
    const float2* x2 = (const float2*)x;
    __half2* xh2 = (__half2*)g_xh;
    for (int j = i; j < NN * 32; j += st) {
        float2 v = x2[j];
        xh2[j] = __floats2half2_rn(v.x, v.y);
    }
}

// ---------------- 1: degree histogram ----------------
__global__ void k_hist(const void* __restrict__ ei) {
    int i = blockIdx.x * blockDim.x + threadIdx.x;
    int st = gridDim.x * blockDim.x;
    for (int e = i; e < EE; e += st) {
        int d = edge_at(ei, EE + e);
        atomicAdd(&g_deg[d], 1);
    }
}

// ---------------- 2: device-wide exclusive scan of g_deg (3 phases) ----------------
__global__ void __launch_bounds__(1024) k_scan_a() {
    __shared__ int sm[1024];
    int tid = threadIdx.x;
    int gid = blockIdx.x * 1024 + tid;
    int v = (gid < NN) ? g_deg[gid] : 0;
    sm[tid] = v;
    __syncthreads();
#pragma unroll
    for (int off = 1; off < 1024; off <<= 1) {
        int t = (tid >= off) ? sm[tid - off] : 0;
        __syncthreads();
        sm[tid] += t;
        __syncthreads();
    }
    if (gid < NN) g_offs[gid] = sm[tid] - v;
    if (tid == 1023) g_bsum[blockIdx.x] = sm[1023];
}

__global__ void __launch_bounds__(128) k_scan_b() {
    __shared__ int sm[128];
    int tid = threadIdx.x;
    int v = (tid < SCAN_BLKS) ? g_bsum[tid] : 0;
    sm[tid] = v;
    __syncthreads();
#pragma unroll
    for (int off = 1; off < 128; off <<= 1) {
        int t = (tid >= off) ? sm[tid - off] : 0;
        __syncthreads();
        sm[tid] += t;
        __syncthreads();
    }
    if (tid < SCAN_BLKS) g_bbase[tid] = sm[tid] - v;
    if (tid == 127) g_offs[NN] = sm[127];
}

__global__ void __launch_bounds__(1024) k_scan_c() {
    int gid = blockIdx.x * 1024 + threadIdx.x;
    if (gid < NN) {
        int o = g_offs[gid] + g_bbase[blockIdx.x];
        g_offs[gid] = o;
        g_cursor[gid] = o;
    }
}

// ---------------- 3: scatter edges into CSR by dst ----------------
__global__ void k_scatter(const void* __restrict__ ei) {
    int i = blockIdx.x * blockDim.x + threadIdx.x;
    int st = gridDim.x * blockDim.x;
    for (int e = i; e < EE; e += st) {
        int s = edge_at(ei, e);
        int d = edge_at(ei, EE + e);
        int pos = atomicAdd(&g_cursor[d], 1);
        g_csr[pos] = s;
    }
}

// ---------------- 4: h = x @ W_att (fp32 math, fp16 store) + logits ----------------
#define FEAT_NPB 64
#define FEAT_BATCH 8
__global__ void __launch_bounds__(128) k_feat(const float* __restrict__ x,
                                              const float* __restrict__ W_att,
                                              const float* __restrict__ a_src,
                                              const float* __restrict__ a_dst) {
    __shared__ float xsh[FEAT_BATCH][64];
    int tid = threadIdx.x;
    int lane = tid & 31;
    int node0 = blockIdx.x * FEAT_NPB;

    for (int hp = 0; hp < 2; hp++) {
        int hh = hp * 2 + (tid >> 6);
        int o = tid & 63;
        float wcol[64];
        const float* wp = W_att + (size_t)hh * 64 * 64 + o;
#pragma unroll
        for (int k = 0; k < 64; k++) wcol[k] = wp[k * 64];
        float av_s = a_src[hh * 64 + o];
        float av_d = a_dst[hh * 64 + o];

        for (int nb = 0; nb < FEAT_NPB; nb += FEAT_BATCH) {
            __syncthreads();
            for (int i = tid; i < FEAT_BATCH * 64; i += 128) {
                int nn = node0 + nb + (i >> 6);
                xsh[i >> 6][i & 63] = (nn < NN) ? x[(size_t)nn * 64 + (i & 63)] : 0.f;
            }
            __syncthreads();
#pragma unroll 1
            for (int bb = 0; bb < FEAT_BATCH; bb++) {
                int n = node0 + nb + bb;
                if (n >= NN) break;
                const float4* xr = (const float4*)xsh[bb];
                // dual accumulators to break the FFMA dependency chain
                float acc0 = 0.f, acc1 = 0.f;
#pragma unroll
                for (int kk = 0; kk < 16; kk += 2) {
                    float4 xv0 = xr[kk];
                    float4 xv1 = xr[kk + 1];
                    acc0 += xv0.x * wcol[kk * 4 + 0];
                    acc0 += xv0.y * wcol[kk * 4 + 1];
                    acc0 += xv0.z * wcol[kk * 4 + 2];
                    acc0 += xv0.w * wcol[kk * 4 + 3];
                    acc1 += xv1.x * wcol[kk * 4 + 4];
                    acc1 += xv1.y * wcol[kk * 4 + 5];
                    acc1 += xv1.z * wcol[kk * 4 + 6];
                    acc1 += xv1.w * wcol[kk * 4 + 7];
                }
                float acc = acc0 + acc1;
                g_h[(size_t)n * 256 + hp * 128 + tid] = __float2half_rn(acc);
                float vs = acc * av_s;
                float vd = acc * av_d;
#pragma unroll
                for (int off = 16; off; off >>= 1) {
                    vs += __shfl_xor_sync(0xFFFFFFFFu, vs, off);
                    vd += __shfl_xor_sync(0xFFFFFFFFu, vd, off);
                }
                if (lane == 0) {
                    atomicAdd(&g_ssrc[n * 4 + hh], vs);
                    atomicAdd(&g_sdst[n * 4 + hh], vd);
                }
            }
        }
    }
}

// ---------------- 5: attention + hop-1, fused, warp per destination node ----------------
// Weights staged in shared memory: lane-parallel pass computes exp weights for a
// chunk of 32 edges (coalesced csr load, 4 MUFU warp-instrs per chunk, no
// shuffles), then a pure load+FMA dissemination loop consumes them via broadcast
// LDS. No max-subtraction (validated: softmax shift-invariant, logits small).
__global__ void __launch_bounds__(256) k_attn() {
    __shared__ int   s_src[8][32];
    __shared__ float s_w[8][32][4];
    int wip = threadIdx.x >> 5;
    int gw = (blockIdx.x * blockDim.x + threadIdx.x) >> 5;
    int lane = threadIdx.x & 31;
    if (gw >= NN) return;
    int n = gw;
    int beg = g_offs[n], end = g_offs[n + 1];
    float4 sd = *(const float4*)&g_sdst[n * 4];
    int hsel = lane >> 3;        // my head for the h-row columns I own

    float ha[8];
#pragma unroll
    for (int i = 0; i < 8; i++) ha[i] = 0.f;
    float dn0 = 0.f, dn1 = 0.f, dn2 = 0.f, dn3 = 0.f;  // lane-local denom partials
    float xa0 = 0.f, xa1 = 0.f;                        // hop-1 partials

    for (int c0 = beg; c0 < end; c0 += 32) {
        int lim = min(32, end - c0);
        // ---- producer pass: one edge per lane ----
        int j = c0 + lane;
        if (j < end) {
            int s = g_csr[j];                              // coalesced
            float4 ss = *(const float4*)&g_ssrc[s * 4];    // scattered 16B
            float w0 = __expf(lrelu(ss.x + sd.x));
            float w1 = __expf(lrelu(ss.y + sd.y));
            float w2 = __expf(lrelu(ss.z + sd.z));
            float w3 = __expf(lrelu(ss.w + sd.w));
            dn0 += w0; dn1 += w1; dn2 += w2; dn3 += w3;
            s_src[wip][lane] = s;
            s_w[wip][lane][0] = w0;
            s_w[wip][lane][1] = w1;
            s_w[wip][lane][2] = w2;
            s_w[wip][lane][3] = w3;
        }
        __syncwarp();
        // ---- dissemination pass: whole warp per edge, pure LDS+LDG+FMA ----
#pragma unroll 4
        for (int k = 0; k < lim; k++) {
            int   s    = s_src[wip][k];
            float wsel = s_w[wip][k][hsel];
            const uint4* hr = (const uint4*)(g_h + (size_t)s * 256);
            uint4 hv = hr[lane];
            unsigned int xv = ((const unsigned int*)(g_xh + (size_t)s * 64))[lane];
            float2 f0 = __half22float2(*(const __half2*)&hv.x);
            float2 f1 = __half22float2(*(const __half2*)&hv.y);
            float2 f2 = __half22float2(*(const __half2*)&hv.z);
            float2 f3 = __half22float2(*(const __half2*)&hv.w);
            ha[0] += wsel * f0.x; ha[1] += wsel * f0.y;
            ha[2] += wsel * f1.x; ha[3] += wsel * f1.y;
            ha[4] += wsel * f2.x; ha[5] += wsel * f2.y;
            ha[6] += wsel * f3.x; ha[7] += wsel * f3.y;
            float2 xf = __half22float2(*(const __half2*)&xv);
            xa0 += xf.x; xa1 += xf.y;
        }
        __syncwarp();
    }

    // reduce denominators across the warp (once per node)
#pragma unroll
    for (int off = 16; off; off >>= 1) {
        dn0 += __shfl_xor_sync(0xFFFFFFFFu, dn0, off);
        dn1 += __shfl_xor_sync(0xFFFFFFFFu, dn1, off);
        dn2 += __shfl_xor_sync(0xFFFFFFFFu, dn2, off);
        dn3 += __shfl_xor_sync(0xFFFFFFFFu, dn3, off);
    }
    float densel = hsel == 0 ? dn0 : hsel == 1 ? dn1 : hsel == 2 ? dn2 : dn3;
    float isel = 1.f / fmaxf(densel, 1e-16f);

    // normalize my head, then mean over heads (lanes differing in bits 3,4)
#pragma unroll
    for (int i = 0; i < 8; i++) {
        float v = ha[i] * isel;
        v += __shfl_xor_sync(0xFFFFFFFFu, v, 8);
        v += __shfl_xor_sync(0xFFFFFFFFu, v, 16);
        ha[i] = 0.25f * v;
    }
    if (lane < 8) {
        float4* dst = (float4*)(g_local + (size_t)n * 64 + 8 * lane);
        dst[0] = make_float4(ha[0], ha[1], ha[2], ha[3]);
        dst[1] = make_float4(ha[4], ha[5], ha[6], ha[7]);
    }
    float invd = 1.f / fmaxf((float)(end - beg), 1.f);
    __half2* g1 = (__half2*)(g_g1h + (size_t)n * 64);
    g1[lane] = __floats2half2_rn(xa0 * invd, xa1 * invd);
}

// ---------------- 6: hop-2 (fp16 gather, fp32 out) ----------------
__global__ void __launch_bounds__(256) k_glob2() {
    int gw = (blockIdx.x * blockDim.x + threadIdx.x) >> 5;
    int lane = threadIdx.x & 31;
    if (gw >= NN) return;
    int n = gw;
    int beg = g_offs[n], end = g_offs[n + 1];
    float a0 = 0.f, a1 = 0.f;
#pragma unroll 4
    for (int j = beg; j < end; j++) {
        int s = g_csr[j];
        const unsigned int* r = (const unsigned int*)(g_g1h + (size_t)s * 64);
        unsigned int v = r[lane];
        float2 f = __half22float2(*(const __half2*)&v);
        a0 += f.x; a1 += f.y;
    }
    float inv = 1.f / fmaxf((float)(end - beg), 1.f);
    float2* dst = (float2*)(g_g2 + (size_t)n * 64 + 2 * lane);
    *dst = make_float2(a0 * inv, a1 * inv);
}

// ---------------- 7: fold W_g into W_w lower half ----------------
__global__ void k_wg(const float* __restrict__ W_g, const float* __restrict__ b_g,
                     const float* __restrict__ W_w, const float* __restrict__ b_w) {
    int i0 = blockIdx.x * blockDim.x + threadIdx.x;
    int st = gridDim.x * blockDim.x;
    for (int idx = i0; idx < 4096; idx += st) {
        int i = idx >> 6, o = idx & 63;
        float s = 0.f;
        for (int k = 0; k < 64; k++)
            s += W_g[i * 64 + k] * W_w[(64 + k) * 64 + o];
        g_W2[idx] = s;
    }
    for (int o = i0; o < 64; o += st) {
        float s = b_w[o];
        for (int k = 0; k < 64; k++)
            s += b_g[k] * W_w[(64 + k) * 64 + o];
        g_b2[o] = s;
    }
}

// ---------------- 8: final projection out = local@W1 + g2@W2 + b2 ----------------
#define FIN_NPB 64
__global__ void __launch_bounds__(256) k_final(const float* __restrict__ W_w,
                                               float* __restrict__ out) {
    __shared__ float W1s[4096];
    __shared__ float W2s[4096];
    __shared__ float bs[64];
    __shared__ float ls[4][64];
    __shared__ float gs[4][64];
    int tid = threadIdx.x;
    for (int i = tid; i < 4096; i += 256) {
        W1s[i] = W_w[i];
        W2s[i] = g_W2[i];
    }
    if (tid < 64) bs[tid] = g_b2[tid];
    __syncthreads();

    int node0 = blockIdx.x * FIN_NPB;
    for (int nb = 0; nb < FIN_NPB; nb += 4) {
        __syncthreads();
        {
            int nn = node0 + nb + (tid >> 6);
            int c = tid & 63;
            if (nn < NN) {
                ls[tid >> 6][c] = g_local[(size_t)nn * 64 + c];
                gs[tid >> 6][c] = g_g2[(size_t)nn * 64 + c];
            }
        }
        __syncthreads();
        int nn = node0 + nb + (tid >> 6);
        if (nn < NN) {
            int o = tid & 63;
            float acc = bs[o];
            const float4* lr = (const float4*)ls[tid >> 6];
            const float4* gr = (const float4*)gs[tid >> 6];
#pragma unroll
            for (int kk = 0; kk < 16; kk++) {
                float4 lv = lr[kk];
                float4 gv = gr[kk];
                acc += lv.x * W1s[(kk * 4 + 0) * 64 + o] + gv.x * W2s[(kk * 4 + 0) * 64 + o];
                acc += lv.y * W1s[(kk * 4 + 1) * 64 + o] + gv.y * W2s[(kk * 4 + 1) * 64 + o];
                acc += lv.z * W1s[(kk * 4 + 2) * 64 + o] + gv.z * W2s[(kk * 4 + 2) * 64 + o];
                acc += lv.w * W1s[(kk * 4 + 3) * 64 + o] + gv.w * W2s[(kk * 4 + 3) * 64 + o];
            }
            out[(size_t)nn * 64 + o] = acc;
        }
    }
}

// ---------------- launch ----------------
extern "C" void kernel_launch(void* const* d_in, const int* in_sizes, int n_in,
                              void* d_out, int out_size) {
    const float* x     = (const float*)d_in[0];
    const void*  ei    = d_in[1];
    const float* W_att = (const float*)d_in[2];
    const float* a_src = (const float*)d_in[3];
    const float* a_dst = (const float*)d_in[4];
    const float* W_g   = (const float*)d_in[5];
    const float* b_g   = (const float*)d_in[6];
    const float* W_w   = (const float*)d_in[7];
    const float* b_w   = (const float*)d_in[8];
    float* out = (float*)d_out;

    k_detect<<<1, 256>>>((const unsigned int*)ei);
    k_init<<<256, 256>>>(x);
    k_hist<<<3125, 256>>>(ei);
    k_scan_a<<<SCAN_BLKS, 1024>>>();
    k_scan_b<<<1, 128>>>();
    k_scan_c<<<SCAN_BLKS, 1024>>>();
    k_scatter<<<3125, 256>>>(ei);
    k_feat<<<(NN + FEAT_NPB - 1) / FEAT_NPB, 128>>>(x, W_att, a_src, a_dst);
    k_attn<<<(NN * 32 + 255) / 256, 256>>>();
    k_glob2<<<(NN * 32 + 255) / 256, 256>>>();
    k_wg<<<17, 256>>>(W_g, b_g, W_w, b_w);
    k_final<<<(NN + FIN_NPB - 1) / FIN_NPB, 256>>>(W_w, out);
}

// round 8
// speedup vs baseline: 1.5154x; 1.0270x over previous
#include <cuda_runtime.h>
#include <cuda_fp16.h>

#define NN 100000
#define EE 800000
#define SCAN_BLKS ((NN + 1023) / 1024)   // 98

// ---------------- scratch (__device__ globals: no allocation allowed) ----------------
__device__ __align__(16) __half g_h[(size_t)NN * 256];   // [N][H*64] transformed feats (fp16)
__device__ __align__(16) __half g_xh[(size_t)NN * 64];   // fp16 copy of x
__device__ __align__(16) __half g_g1h[(size_t)NN * 64];  // hop-1 aggregate (fp16)
__device__ float g_local[(size_t)NN * 64];   // attention output (head-mean)
__device__ float g_g2[(size_t)NN * 64];      // hop-2 aggregate
__device__ __align__(16) float g_ssrc[NN * 4];           // per-node src logits [N][H]
__device__ __align__(16) float g_sdst[NN * 4];           // per-node dst logits [N][H]
__device__ int   g_deg[NN];
__device__ int   g_offs[NN + 1];
__device__ int   g_cursor[NN];
__device__ int   g_csr[EE];                  // src node per CSR slot (sorted by dst)
__device__ float g_W2[64 * 64];              // W_g @ W_w[64:128]
__device__ float g_b2[64];                   // b_g @ W_w[64:128] + b_w
__device__ float g_V[64 * 8];                // folded logit vectors: V[i][j] (j<4 src, j>=4 dst)
__device__ int   g_is64;                     // edge_index dtype flag
__device__ int   g_bsum[SCAN_BLKS];
__device__ int   g_bbase[SCAN_BLKS];

__device__ __forceinline__ float lrelu(float v) { return v > 0.f ? v : 0.2f * v; }

// ---------------- detect edge_index dtype (int32 vs int64) ----------------
__global__ void k_detect(const unsigned int* __restrict__ w) {
    __shared__ int allzero;
    if (threadIdx.x == 0) allzero = 1;
    __syncthreads();
    for (int i = threadIdx.x; i < 1024; i += blockDim.x)
        if (w[2 * i + 1] != 0u) allzero = 0;
    __syncthreads();
    if (threadIdx.x == 0) g_is64 = allzero;
}

__device__ __forceinline__ int edge_at(const void* ei, int idx) {
    if (g_is64) return (int)((const long long*)ei)[idx];
    return ((const int*)ei)[idx];
}

// ---------------- init: zero degrees + fp16 copy of x ----------------
__global__ void k_init(const float* __restrict__ x) {
    int i = blockIdx.x * blockDim.x + threadIdx.x;
    int st = gridDim.x * blockDim.x;
    for (int j = i; j < NN; j += st) g_deg[j] = 0;
    const float2* x2 = (const float2*)x;
    __half2* xh2 = (__half2*)g_xh;
    for (int j = i; j < NN * 32; j += st) {
        float2 v = x2[j];
        xh2[j] = __floats2half2_rn(v.x, v.y);
    }
}

// ---------------- degree histogram ----------------
__global__ void k_hist(const void* __restrict__ ei) {
    int i = blockIdx.x * blockDim.x + threadIdx.x;
    int st = gridDim.x * blockDim.x;
    for (int e = i; e < EE; e += st) {
        int d = edge_at(ei, EE + e);
        atomicAdd(&g_deg[d], 1);
    }
}

// ---------------- h = x @ W_att (pure GEMM now; fp32 math, fp16 store) ----------------
#define FEAT_NPB 64
#define FEAT_BATCH 8
__global__ void __launch_bounds__(128) k_feat(const float* __restrict__ x,
                                              const float* __restrict__ W_att) {
    __shared__ float xsh[FEAT_BATCH][64];
    int tid = threadIdx.x;
    int node0 = blockIdx.x * FEAT_NPB;

    for (int hp = 0; hp < 2; hp++) {
        int hh = hp * 2 + (tid >> 6);
        int o = tid & 63;
        float wcol[64];
        const float* wp = W_att + (size_t)hh * 64 * 64 + o;
#pragma unroll
        for (int k = 0; k < 64; k++) wcol[k] = wp[k * 64];

        for (int nb = 0; nb < FEAT_NPB; nb += FEAT_BATCH) {
            __syncthreads();
            for (int i = tid; i < FEAT_BATCH * 64; i += 128) {
                int nn = node0 + nb + (i >> 6);
                xsh[i >> 6][i & 63] = (nn < NN) ? x[(size_t)nn * 64 + (i & 63)] : 0.f;
            }
            __syncthreads();
#pragma unroll 1
            for (int bb = 0; bb < FEAT_BATCH; bb++) {
                int n = node0 + nb + bb;
                if (n >= NN) break;
                const float4* xr = (const float4*)xsh[bb];
                float acc0 = 0.f, acc1 = 0.f;
#pragma unroll
                for (int kk = 0; kk < 16; kk += 2) {
                    float4 xv0 = xr[kk];
                    float4 xv1 = xr[kk + 1];
                    acc0 += xv0.x * wcol[kk * 4 + 0];
                    acc0 += xv0.y * wcol[kk * 4 + 1];
                    acc0 += xv0.z * wcol[kk * 4 + 2];
                    acc0 += xv0.w * wcol[kk * 4 + 3];
                    acc1 += xv1.x * wcol[kk * 4 + 4];
                    acc1 += xv1.y * wcol[kk * 4 + 5];
                    acc1 += xv1.z * wcol[kk * 4 + 6];
                    acc1 += xv1.w * wcol[kk * 4 + 7];
                }
                g_h[(size_t)n * 256 + hp * 128 + tid] = __float2half_rn(acc0 + acc1);
            }
        }
    }
}

// ---------------- fold logit vectors: V[i][j] = sum_o W_att[h][i][o]*a[h][o] ----------------
__global__ void k_fold(const float* __restrict__ W_att, const float* __restrict__ a_src,
                       const float* __restrict__ a_dst) {
    int t = threadIdx.x;            // 512 threads: t = i*8 + j
    int i = t >> 3, j = t & 7;
    int h = j & 3;
    const float* a = (j < 4) ? (a_src + h * 64) : (a_dst + h * 64);
    const float* w = W_att + (size_t)h * 4096 + i * 64;
    float s0 = 0.f, s1 = 0.f;
#pragma unroll
    for (int o = 0; o < 64; o += 2) { s0 += w[o] * a[o]; s1 += w[o + 1] * a[o + 1]; }
    g_V[i * 8 + j] = s0 + s1;
}

// ---------------- logits: s[n][j] = x[n] . V[:,j]  (warp per node, no atomics) ----------------
__global__ void __launch_bounds__(256) k_logit(const float* __restrict__ x) {
    __shared__ float Vs[512];
    int tid = threadIdx.x;
    for (int i = tid; i < 512; i += 256) Vs[i] = g_V[i];
    __syncthreads();
    int gw = (blockIdx.x * blockDim.x + tid) >> 5;
    int lane = tid & 31;
    if (gw >= NN) return;
    float2 xv = ((const float2*)(x + (size_t)gw * 64))[lane];
    float p[8];
#pragma unroll
    for (int j = 0; j < 8; j++)
        p[j] = xv.x * Vs[(2 * lane) * 8 + j] + xv.y * Vs[(2 * lane + 1) * 8 + j];
#pragma unroll
    for (int j = 0; j < 8; j++) {
#pragma unroll
        for (int off = 16; off; off >>= 1)
            p[j] += __shfl_xor_sync(0xFFFFFFFFu, p[j], off);
    }
    if (lane == 0) {
        *(float4*)&g_ssrc[gw * 4] = make_float4(p[0], p[1], p[2], p[3]);
        *(float4*)&g_sdst[gw * 4] = make_float4(p[4], p[5], p[6], p[7]);
    }
}

// ---------------- device-wide exclusive scan of g_deg (3 phases) ----------------
__global__ void __launch_bounds__(1024) k_scan_a() {
    __shared__ int sm[1024];
    int tid = threadIdx.x;
    int gid = blockIdx.x * 1024 + tid;
    int v = (gid < NN) ? g_deg[gid] : 0;
    sm[tid] = v;
    __syncthreads();
#pragma unroll
    for (int off = 1; off < 1024; off <<= 1) {
        int t = (tid >= off) ? sm[tid - off] : 0;
        __syncthreads();
        sm[tid] += t;
        __syncthreads();
    }
    if (gid < NN) g_offs[gid] = sm[tid] - v;
    if (tid == 1023) g_bsum[blockIdx.x] = sm[1023];
}

__global__ void __launch_bounds__(128) k_scan_b() {
    __shared__ int sm[128];
    int tid = threadIdx.x;
    int v = (tid < SCAN_BLKS) ? g_bsum[tid] : 0;
    sm[tid] = v;
    __syncthreads();
#pragma unroll
    for (int off = 1; off < 128; off <<= 1) {
        int t = (tid >= off) ? sm[tid - off] : 0;
        __syncthreads();
        sm[tid] += t;
        __syncthreads();
    }
    if (tid < SCAN_BLKS) g_bbase[tid] = sm[tid] - v;
    if (tid == 127) g_offs[NN] = sm[127];
}

__global__ void __launch_bounds__(1024) k_scan_c() {
    int gid = blockIdx.x * 1024 + threadIdx.x;
    if (gid < NN) {
        int o = g_offs[gid] + g_bbase[blockIdx.x];
        g_offs[gid] = o;
        g_cursor[gid] = o;
    }
}

// ---------------- scatter edges into CSR by dst ----------------
__global__ void k_scatter(const void* __restrict__ ei) {
    int i = blockIdx.x * blockDim.x + threadIdx.x;
    int st = gridDim.x * blockDim.x;
    for (int e = i; e < EE; e += st) {
        int s = edge_at(ei, e);
        int d = edge_at(ei, EE + e);
        int pos = atomicAdd(&g_cursor[d], 1);
        g_csr[pos] = s;
    }
}

// ---------------- attention + hop-1, fused, warp per destination node ----------------
__global__ void __launch_bounds__(256) k_attn() {
    __shared__ int   s_src[8][32];
    __shared__ float s_w[8][32][4];
    int wip = threadIdx.x >> 5;
    int gw = (blockIdx.x * blockDim.x + threadIdx.x) >> 5;
    int lane = threadIdx.x & 31;
    if (gw >= NN) return;
    int n = gw;
    int beg = g_offs[n], end = g_offs[n + 1];
    float4 sd = *(const float4*)&g_sdst[n * 4];
    int hsel = lane >> 3;

    float ha[8];
#pragma unroll
    for (int i = 0; i < 8; i++) ha[i] = 0.f;
    float dn0 = 0.f, dn1 = 0.f, dn2 = 0.f, dn3 = 0.f;
    float xa0 = 0.f, xa1 = 0.f;

    for (int c0 = beg; c0 < end; c0 += 32) {
        int lim = min(32, end - c0);
        int j = c0 + lane;
        if (j < end) {
            int s = g_csr[j];
            float4 ss = *(const float4*)&g_ssrc[s * 4];
            float w0 = __expf(lrelu(ss.x + sd.x));
            float w1 = __expf(lrelu(ss.y + sd.y));
            float w2 = __expf(lrelu(ss.z + sd.z));
            float w3 = __expf(lrelu(ss.w + sd.w));
            dn0 += w0; dn1 += w1; dn2 += w2; dn3 += w3;
            s_src[wip][lane] = s;
            s_w[wip][lane][0] = w0;
            s_w[wip][lane][1] = w1;
            s_w[wip][lane][2] = w2;
            s_w[wip][lane][3] = w3;
        }
        __syncwarp();
#pragma unroll 4
        for (int k = 0; k < lim; k++) {
            int   s    = s_src[wip][k];
            float wsel = s_w[wip][k][hsel];
            const uint4* hr = (const uint4*)(g_h + (size_t)s * 256);
            uint4 hv = hr[lane];
            unsigned int xv = ((const unsigned int*)(g_xh + (size_t)s * 64))[lane];
            float2 f0 = __half22float2(*(const __half2*)&hv.x);
            float2 f1 = __half22float2(*(const __half2*)&hv.y);
            float2 f2 = __half22float2(*(const __half2*)&hv.z);
            float2 f3 = __half22float2(*(const __half2*)&hv.w);
            ha[0] += wsel * f0.x; ha[1] += wsel * f0.y;
            ha[2] += wsel * f1.x; ha[3] += wsel * f1.y;
            ha[4] += wsel * f2.x; ha[5] += wsel * f2.y;
            ha[6] += wsel * f3.x; ha[7] += wsel * f3.y;
            float2 xf = __half22float2(*(const __half2*)&xv);
            xa0 += xf.x; xa1 += xf.y;
        }
        __syncwarp();
    }

#pragma unroll
    for (int off = 16; off; off >>= 1) {
        dn0 += __shfl_xor_sync(0xFFFFFFFFu, dn0, off);
        dn1 += __shfl_xor_sync(0xFFFFFFFFu, dn1, off);
        dn2 += __shfl_xor_sync(0xFFFFFFFFu, dn2, off);
        dn3 += __shfl_xor_sync(0xFFFFFFFFu, dn3, off);
    }
    float densel = hsel == 0 ? dn0 : hsel == 1 ? dn1 : hsel == 2 ? dn2 : dn3;
    float isel = 1.f / fmaxf(densel, 1e-16f);

#pragma unroll
    for (int i = 0; i < 8; i++) {
        float v = ha[i] * isel;
        v += __shfl_xor_sync(0xFFFFFFFFu, v, 8);
        v += __shfl_xor_sync(0xFFFFFFFFu, v, 16);
        ha[i] = 0.25f * v;
    }
    if (lane < 8) {
        float4* dst = (float4*)(g_local + (size_t)n * 64 + 8 * lane);
        dst[0] = make_float4(ha[0], ha[1], ha[2], ha[3]);
        dst[1] = make_float4(ha[4], ha[5], ha[6], ha[7]);
    }
    float invd = 1.f / fmaxf((float)(end - beg), 1.f);
    __half2* g1 = (__half2*)(g_g1h + (size_t)n * 64);
    g1[lane] = __floats2half2_rn(xa0 * invd, xa1 * invd);
}

// ---------------- hop-2 (fp16 gather, fp32 out) ----------------
__global__ void __launch_bounds__(256) k_glob2() {
    int gw = (blockIdx.x * blockDim.x + threadIdx.x) >> 5;
    int lane = threadIdx.x & 31;
    if (gw >= NN) return;
    int n = gw;
    int beg = g_offs[n], end = g_offs[n + 1];
    float a0 = 0.f, a1 = 0.f;
#pragma unroll 4
    for (int j = beg; j < end; j++) {
        int s = g_csr[j];
        const unsigned int* r = (const unsigned int*)(g_g1h + (size_t)s * 64);
        unsigned int v = r[lane];
        float2 f = __half22float2(*(const __half2*)&v);
        a0 += f.x; a1 += f.y;
    }
    float inv = 1.f / fmaxf((float)(end - beg), 1.f);
    float2* dst = (float2*)(g_g2 + (size_t)n * 64 + 2 * lane);
    *dst = make_float2(a0 * inv, a1 * inv);
}

// ---------------- fold W_g into W_w lower half ----------------
__global__ void k_wg(const float* __restrict__ W_g, const float* __restrict__ b_g,
                     const float* __restrict__ W_w, const float* __restrict__ b_w) {
    int i0 = blockIdx.x * blockDim.x + threadIdx.x;
    int st = gridDim.x * blockDim.x;
    for (int idx = i0; idx < 4096; idx += st) {
        int i = idx >> 6, o = idx & 63;
        float s = 0.f;
        for (int k = 0; k < 64; k++)
            s += W_g[i * 64 + k] * W_w[(64 + k) * 64 + o];
        g_W2[idx] = s;
    }
    for (int o = i0; o < 64; o += st) {
        float s = b_w[o];
        for (int k = 0; k < 64; k++)
            s += b_g[k] * W_w[(64 + k) * 64 + o];
        g_b2[o] = s;
    }
}

// ---------------- final projection out = local@W1 + g2@W2 + b2 ----------------
#define FIN_NPB 64
__global__ void __launch_bounds__(256) k_final(const float* __restrict__ W_w,
                                               float* __restrict__ out) {
    __shared__ float W1s[4096];
    __shared__ float W2s[4096];
    __shared__ float bs[64];
    __shared__ float ls[4][64];
    __shared__ float gs[4][64];
    int tid = threadIdx.x;
    for (int i = tid; i < 4096; i += 256) {
        W1s[i] = W_w[i];
        W2s[i] = g_W2[i];
    }
    if (tid < 64) bs[tid] = g_b2[tid];
    __syncthreads();

    int node0 = blockIdx.x * FIN_NPB;
    for (int nb = 0; nb < FIN_NPB; nb += 4) {
        __syncthreads();
        {
            int nn = node0 + nb + (tid >> 6);
            int c = tid & 63;
            if (nn < NN) {
                ls[tid >> 6][c] = g_local[(size_t)nn * 64 + c];
                gs[tid >> 6][c] = g_g2[(size_t)nn * 64 + c];
            }
        }
        __syncthreads();
        int nn = node0 + nb + (tid >> 6);
        if (nn < NN) {
            int o = tid & 63;
            float aA = bs[o], aB = 0.f, aC = 0.f, aD = 0.f;
            const float4* lr = (const float4*)ls[tid >> 6];
            const float4* gr = (const float4*)gs[tid >> 6];
#pragma unroll
            for (int kk = 0; kk < 16; kk += 2) {
                float4 lv0 = lr[kk], lv1 = lr[kk + 1];
                float4 gv0 = gr[kk], gv1 = gr[kk + 1];
                aA += lv0.x * W1s[(kk * 4 + 0) * 64 + o];
                aA += lv0.y * W1s[(kk * 4 + 1) * 64 + o];
                aA += lv0.z * W1s[(kk * 4 + 2) * 64 + o];
                aA += lv0.w * W1s[(kk * 4 + 3) * 64 + o];
                aB += lv1.x * W1s[(kk * 4 + 4) * 64 + o];
                aB += lv1.y * W1s[(kk * 4 + 5) * 64 + o];
                aB += lv1.z * W1s[(kk * 4 + 6) * 64 + o];
                aB += lv1.w * W1s[(kk * 4 + 7) * 64 + o];
                aC += gv0.x * W2s[(kk * 4 + 0) * 64 + o];
                aC += gv0.y * W2s[(kk * 4 + 1) * 64 + o];
                aC += gv0.z * W2s[(kk * 4 + 2) * 64 + o];
                aC += gv0.w * W2s[(kk * 4 + 3) * 64 + o];
                aD += gv1.x * W2s[(kk * 4 + 4) * 64 + o];
                aD += gv1.y * W2s[(kk * 4 + 5) * 64 + o];
                aD += gv1.z * W2s[(kk * 4 + 6) * 64 + o];
                aD += gv1.w * W2s[(kk * 4 + 7) * 64 + o];
            }
            out[(size_t)nn * 64 + o] = (aA + aB) + (aC + aD);
        }
    }
}

// ---------------- launch ----------------
extern "C" void kernel_launch(void* const* d_in, const int* in_sizes, int n_in,
                              void* d_out, int out_size) {
    const float* x     = (const float*)d_in[0];
    const void*  ei    = d_in[1];
    const float* W_att = (const float*)d_in[2];
    const float* a_src = (const float*)d_in[3];
    const float* a_dst = (const float*)d_in[4];
    const float* W_g   = (const float*)d_in[5];
    const float* b_g   = (const float*)d_in[6];
    const float* W_w   = (const float*)d_in[7];
    const float* b_w   = (const float*)d_in[8];
    float* out = (float*)d_out;

    // k_feat placed 4th so the profiler slot (4th launch) captures it next round.
    k_detect<<<1, 256>>>((const unsigned int*)ei);
    k_init<<<256, 256>>>(x);
    k_hist<<<3125, 256>>>(ei);
    k_feat<<<(NN + FEAT_NPB - 1) / FEAT_NPB, 128>>>(x, W_att);
    k_fold<<<1, 512>>>(W_att, a_src, a_dst);
    k_logit<<<(NN * 32 + 255) / 256, 256>>>(x);
    k_scan_a<<<SCAN_BLKS, 1024>>>();
    k_scan_b<<<1, 128>>>();
    k_scan_c<<<SCAN_BLKS, 1024>>>();
    k_scatter<<<3125, 256>>>(ei);
    k_attn<<<(NN * 32 + 255) / 256, 256>>>();
    k_glob2<<<(NN * 32 + 255) / 256, 256>>>();
    k_wg<<<17, 256>>>(W_g, b_g, W_w, b_w);
    k_final<<<(NN + FIN_NPB - 1) / FIN_NPB, 256>>>(W_w, out);
}

// round 9
// speedup vs baseline: 1.5909x; 1.0498x over previous
#include <cuda_runtime.h>
#include <cuda_fp16.h>

#define NN 100000
#define EE 800000
#define SCAN_BLKS ((NN + 1023) / 1024)   // 98

// ---------------- scratch (__device__ globals: no allocation allowed) ----------------
__device__ __align__(16) __half g_h[(size_t)NN * 256];   // [N][H*64] transformed feats (fp16)
__device__ __align__(16) __half g_xh[(size_t)NN * 64];   // fp16 copy of x
__device__ __align__(16) __half g_g1h[(size_t)NN * 64];  // hop-1 aggregate (fp16)
__device__ float g_local[(size_t)NN * 64];   // attention output (head-mean)
__device__ float g_g2[(size_t)NN * 64];      // hop-2 aggregate
__device__ __align__(16) float g_ssrc[NN * 4];           // per-node src logits [N][H]
__device__ __align__(16) float g_sdst[NN * 4];           // per-node dst logits [N][H]
__device__ int   g_deg[NN];
__device__ int   g_offs[NN + 1];
__device__ int   g_cursor[NN];
__device__ int   g_csr[EE];                  // src node per CSR slot (sorted by dst)
__device__ float g_W2[64 * 64];              // W_g @ W_w[64:128]
__device__ float g_b2[64];                   // b_g @ W_w[64:128] + b_w
__device__ float g_V[64 * 8];                // folded logit vectors: V[i][j] (j<4 src, j>=4 dst)
__device__ int   g_is64;                     // edge_index dtype flag
__device__ int   g_bsum[SCAN_BLKS];
__device__ int   g_bbase[SCAN_BLKS];

__device__ __forceinline__ float lrelu(float v) { return v > 0.f ? v : 0.2f * v; }

// ---------------- detect edge_index dtype (int32 vs int64) ----------------
__global__ void k_detect(const unsigned int* __restrict__ w) {
    __shared__ int allzero;
    if (threadIdx.x == 0) allzero = 1;
    __syncthreads();
    for (int i = threadIdx.x; i < 1024; i += blockDim.x)
        if (w[2 * i + 1] != 0u) allzero = 0;
    __syncthreads();
    if (threadIdx.x == 0) g_is64 = allzero;
}

__device__ __forceinline__ int edge_at(const void* ei, int idx) {
    if (g_is64) return (int)((const long long*)ei)[idx];
    return ((const int*)ei)[idx];
}

// ---------------- init: zero degrees + fp16 copy of x ----------------
__global__ void k_init(const float* __restrict__ x) {
    int i = blockIdx.x * blockDim.x + threadIdx.x;
    int st = gridDim.x * blockDim.x;
    for (int j = i; j < NN; j += st) g_deg[j] = 0;
    const float2* x2 = (const float2*)x;
    __half2* xh2 = (__half2*)g_xh;
    for (int j = i; j < NN * 32; j += st) {
        float2 v = x2[j];
        xh2[j] = __floats2half2_rn(v.x, v.y);
    }
}

// ---------------- degree histogram ----------------
__global__ void k_hist(const void* __restrict__ ei) {
    int i = blockIdx.x * blockDim.x + threadIdx.x;
    int st = gridDim.x * blockDim.x;
    for (int e = i; e < EE; e += st) {
        int d = edge_at(ei, EE + e);
        atomicAdd(&g_deg[d], 1);
    }
}

// ---------------- h = x @ W_att — register-blocked GEMM (8x8 per thread) ----------------
// Block: 256 threads -> tile 64 nodes x 256 cols, K=64.
// smem (dynamic): asmT[64][68] (x transposed, padded) + Ws[64][256] (W re-laid).
#define FEAT_NPB 64
#define ASTRIDE 68
__global__ void __launch_bounds__(256) k_feat(const float* __restrict__ x,
                                              const float* __restrict__ W_att) {
    extern __shared__ float dsm[];
    float* asmT = dsm;                    // [64][ASTRIDE]
    float* Ws   = dsm + 64 * ASTRIDE;     // [64][256]
    int tid = threadIdx.x;
    int node0 = blockIdx.x * FEAT_NPB;

    // stage W: Ws[k][h*64+o] = W_att[h][k][o]
    for (int idx = tid; idx < 64 * 256; idx += 256) {
        int k = idx >> 8, c = idx & 255;
        int h = c >> 6, o = c & 63;
        Ws[idx] = W_att[(size_t)h * 4096 + k * 64 + o];
    }
    // stage x transposed: asmT[k][n] = x[node0+n][k] (zero-pad OOB)
    for (int idx = tid; idx < 64 * 64; idx += 256) {
        int n = idx >> 6, k = idx & 63;
        int nn = node0 + n;
        asmT[k * ASTRIDE + n] = (nn < NN) ? x[(size_t)nn * 64 + k] : 0.f;
    }
    __syncthreads();

    int tx = tid & 31, ty = tid >> 5;
    int c0 = tx * 8;        // my 8 columns
    int n0 = ty * 8;        // my 8 nodes

    float acc[8][8];
#pragma unroll
    for (int i = 0; i < 8; i++)
#pragma unroll
        for (int j = 0; j < 8; j++) acc[i][j] = 0.f;

#pragma unroll 4
    for (int k = 0; k < 64; k++) {
        float4 a0 = *(const float4*)&asmT[k * ASTRIDE + n0];
        float4 a1 = *(const float4*)&asmT[k * ASTRIDE + n0 + 4];
        float4 b0 = *(const float4*)&Ws[k * 256 + c0];
        float4 b1 = *(const float4*)&Ws[k * 256 + c0 + 4];
        float av[8] = {a0.x, a0.y, a0.z, a0.w, a1.x, a1.y, a1.z, a1.w};
        float bv[8] = {b0.x, b0.y, b0.z, b0.w, b1.x, b1.y, b1.z, b1.w};
#pragma unroll
        for (int i = 0; i < 8; i++)
#pragma unroll
            for (int j = 0; j < 8; j++) acc[i][j] += av[i] * bv[j];
    }

    // epilogue: fp16, one 16B store per node row
#pragma unroll
    for (int i = 0; i < 8; i++) {
        int nn = node0 + n0 + i;
        if (nn < NN) {
            __half2 h0 = __floats2half2_rn(acc[i][0], acc[i][1]);
            __half2 h1 = __floats2half2_rn(acc[i][2], acc[i][3]);
            __half2 h2 = __floats2half2_rn(acc[i][4], acc[i][5]);
            __half2 h3 = __floats2half2_rn(acc[i][6], acc[i][7]);
            uint4 v;
            v.x = *(unsigned int*)&h0;
            v.y = *(unsigned int*)&h1;
            v.z = *(unsigned int*)&h2;
            v.w = *(unsigned int*)&h3;
            *(uint4*)&g_h[(size_t)nn * 256 + c0] = v;
        }
    }
}

// ---------------- fold logit vectors: V[i][j] = sum_o W_att[h][i][o]*a[h][o] ----------------
__global__ void k_fold(const float* __restrict__ W_att, const float* __restrict__ a_src,
                       const float* __restrict__ a_dst) {
    int t = threadIdx.x;            // 512 threads: t = i*8 + j
    int i = t >> 3, j = t & 7;
    int h = j & 3;
    const float* a = (j < 4) ? (a_src + h * 64) : (a_dst + h * 64);
    const float* w = W_att + (size_t)h * 4096 + i * 64;
    float s0 = 0.f, s1 = 0.f;
#pragma unroll
    for (int o = 0; o < 64; o += 2) { s0 += w[o] * a[o]; s1 += w[o + 1] * a[o + 1]; }
    g_V[i * 8 + j] = s0 + s1;
}

// ---------------- logits: s[n][j] = x[n] . V[:,j]  (warp per node, no atomics) ----------------
__global__ void __launch_bounds__(256) k_logit(const float* __restrict__ x) {
    __shared__ float Vs[512];
    int tid = threadIdx.x;
    for (int i = tid; i < 512; i += 256) Vs[i] = g_V[i];
    __syncthreads();
    int gw = (blockIdx.x * blockDim.x + tid) >> 5;
    int lane = tid & 31;
    if (gw >= NN) return;
    float2 xv = ((const float2*)(x + (size_t)gw * 64))[lane];
    float p[8];
#pragma unroll
    for (int j = 0; j < 8; j++)
        p[j] = xv.x * Vs[(2 * lane) * 8 + j] + xv.y * Vs[(2 * lane + 1) * 8 + j];
#pragma unroll
    for (int j = 0; j < 8; j++) {
#pragma unroll
        for (int off = 16; off; off >>= 1)
            p[j] += __shfl_xor_sync(0xFFFFFFFFu, p[j], off);
    }
    if (lane == 0) {
        *(float4*)&g_ssrc[gw * 4] = make_float4(p[0], p[1], p[2], p[3]);
        *(float4*)&g_sdst[gw * 4] = make_float4(p[4], p[5], p[6], p[7]);
    }
}

// ---------------- device-wide exclusive scan of g_deg (3 phases) ----------------
__global__ void __launch_bounds__(1024) k_scan_a() {
    __shared__ int sm[1024];
    int tid = threadIdx.x;
    int gid = blockIdx.x * 1024 + tid;
    int v = (gid < NN) ? g_deg[gid] : 0;
    sm[tid] = v;
    __syncthreads();
#pragma unroll
    for (int off = 1; off < 1024; off <<= 1) {
        int t = (tid >= off) ? sm[tid - off] : 0;
        __syncthreads();
        sm[tid] += t;
        __syncthreads();
    }
    if (gid < NN) g_offs[gid] = sm[tid] - v;
    if (tid == 1023) g_bsum[blockIdx.x] = sm[1023];
}

__global__ void __launch_bounds__(128) k_scan_b() {
    __shared__ int sm[128];
    int tid = threadIdx.x;
    int v = (tid < SCAN_BLKS) ? g_bsum[tid] : 0;
    sm[tid] = v;
    __syncthreads();
#pragma unroll
    for (int off = 1; off < 128; off <<= 1) {
        int t = (tid >= off) ? sm[tid - off] : 0;
        __syncthreads();
        sm[tid] += t;
        __syncthreads();
    }
    if (tid < SCAN_BLKS) g_bbase[tid] = sm[tid] - v;
    if (tid == 127) g_offs[NN] = sm[127];
}

__global__ void __launch_bounds__(1024) k_scan_c() {
    int gid = blockIdx.x * 1024 + threadIdx.x;
    if (gid < NN) {
        int o = g_offs[gid] + g_bbase[blockIdx.x];
        g_offs[gid] = o;
        g_cursor[gid] = o;
    }
}

// ---------------- scatter edges into CSR by dst ----------------
__global__ void k_scatter(const void* __restrict__ ei) {
    int i = blockIdx.x * blockDim.x + threadIdx.x;
    int st = gridDim.x * blockDim.x;
    for (int e = i; e < EE; e += st) {
        int s = edge_at(ei, e);
        int d = edge_at(ei, EE + e);
        int pos = atomicAdd(&g_cursor[d], 1);
        g_csr[pos] = s;
    }
}

// ---------------- attention + hop-1, fused, warp per destination node ----------------
__global__ void __launch_bounds__(256) k_attn() {
    __shared__ int   s_src[8][32];
    __shared__ float s_w[8][32][4];
    int wip = threadIdx.x >> 5;
    int gw = (blockIdx.x * blockDim.x + threadIdx.x) >> 5;
    int lane = threadIdx.x & 31;
    if (gw >= NN) return;
    int n = gw;
    int beg = g_offs[n], end = g_offs[n + 1];
    float4 sd = *(const float4*)&g_sdst[n * 4];
    int hsel = lane >> 3;

    float ha[8];
#pragma unroll
    for (int i = 0; i < 8; i++) ha[i] = 0.f;
    float dn0 = 0.f, dn1 = 0.f, dn2 = 0.f, dn3 = 0.f;
    float xa0 = 0.f, xa1 = 0.f;

    for (int c0 = beg; c0 < end; c0 += 32) {
        int lim = min(32, end - c0);
        int j = c0 + lane;
        if (j < end) {
            int s = g_csr[j];
            float4 ss = *(const float4*)&g_ssrc[s * 4];
            float w0 = __expf(lrelu(ss.x + sd.x));
            float w1 = __expf(lrelu(ss.y + sd.y));
            float w2 = __expf(lrelu(ss.z + sd.z));
            float w3 = __expf(lrelu(ss.w + sd.w));
            dn0 += w0; dn1 += w1; dn2 += w2; dn3 += w3;
            s_src[wip][lane] = s;
            s_w[wip][lane][0] = w0;
            s_w[wip][lane][1] = w1;
            s_w[wip][lane][2] = w2;
            s_w[wip][lane][3] = w3;
        }
        __syncwarp();
#pragma unroll 4
        for (int k = 0; k < lim; k++) {
            int   s    = s_src[wip][k];
            float wsel = s_w[wip][k][hsel];
            const uint4* hr = (const uint4*)(g_h + (size_t)s * 256);
            uint4 hv = hr[lane];
            unsigned int xv = ((const unsigned int*)(g_xh + (size_t)s * 64))[lane];
            float2 f0 = __half22float2(*(const __half2*)&hv.x);
            float2 f1 = __half22float2(*(const __half2*)&hv.y);
            float2 f2 = __half22float2(*(const __half2*)&hv.z);
            float2 f3 = __half22float2(*(const __half2*)&hv.w);
            ha[0] += wsel * f0.x; ha[1] += wsel * f0.y;
            ha[2] += wsel * f1.x; ha[3] += wsel * f1.y;
            ha[4] += wsel * f2.x; ha[5] += wsel * f2.y;
            ha[6] += wsel * f3.x; ha[7] += wsel * f3.y;
            float2 xf = __half22float2(*(const __half2*)&xv);
            xa0 += xf.x; xa1 += xf.y;
        }
        __syncwarp();
    }

#pragma unroll
    for (int off = 16; off; off >>= 1) {
        dn0 += __shfl_xor_sync(0xFFFFFFFFu, dn0, off);
        dn1 += __shfl_xor_sync(0xFFFFFFFFu, dn1, off);
        dn2 += __shfl_xor_sync(0xFFFFFFFFu, dn2, off);
        dn3 += __shfl_xor_sync(0xFFFFFFFFu, dn3, off);
    }
    float densel = hsel == 0 ? dn0 : hsel == 1 ? dn1 : hsel == 2 ? dn2 : dn3;
    float isel = 1.f / fmaxf(densel, 1e-16f);

#pragma unroll
    for (int i = 0; i < 8; i++) {
        float v = ha[i] * isel;
        v += __shfl_xor_sync(0xFFFFFFFFu, v, 8);
        v += __shfl_xor_sync(0xFFFFFFFFu, v, 16);
        ha[i] = 0.25f * v;
    }
    if (lane < 8) {
        float4* dst = (float4*)(g_local + (size_t)n * 64 + 8 * lane);
        dst[0] = make_float4(ha[0], ha[1], ha[2], ha[3]);
        dst[1] = make_float4(ha[4], ha[5], ha[6], ha[7]);
    }
    float invd = 1.f / fmaxf((float)(end - beg), 1.f);
    __half2* g1 = (__half2*)(g_g1h + (size_t)n * 64);
    g1[lane] = __floats2half2_rn(xa0 * invd, xa1 * invd);
}

// ---------------- hop-2 (fp16 gather, fp32 out) ----------------
__global__ void __launch_bounds__(256) k_glob2() {
    int gw = (blockIdx.x * blockDim.x + threadIdx.x) >> 5;
    int lane = threadIdx.x & 31;
    if (gw >= NN) return;
    int n = gw;
    int beg = g_offs[n], end = g_offs[n + 1];
    float a0 = 0.f, a1 = 0.f;
#pragma unroll 4
    for (int j = beg; j < end; j++) {
        int s = g_csr[j];
        const unsigned int* r = (const unsigned int*)(g_g1h + (size_t)s * 64);
        unsigned int v = r[lane];
        float2 f = __half22float2(*(const __half2*)&v);
        a0 += f.x; a1 += f.y;
    }
    float inv = 1.f / fmaxf((float)(end - beg), 1.f);
    float2* dst = (float2*)(g_g2 + (size_t)n * 64 + 2 * lane);
    *dst = make_float2(a0 * inv, a1 * inv);
}

// ---------------- fold W_g into W_w lower half ----------------
__global__ void k_wg(const float* __restrict__ W_g, const float* __restrict__ b_g,
                     const float* __restrict__ W_w, const float* __restrict__ b_w) {
    int i0 = blockIdx.x * blockDim.x + threadIdx.x;
    int st = gridDim.x * blockDim.x;
    for (int idx = i0; idx < 4096; idx += st) {
        int i = idx >> 6, o = idx & 63;
        float s = 0.f;
        for (int k = 0; k < 64; k++)
            s += W_g[i * 64 + k] * W_w[(64 + k) * 64 + o];
        g_W2[idx] = s;
    }
    for (int o = i0; o < 64; o += st) {
        float s = b_w[o];
        for (int k = 0; k < 64; k++)
            s += b_g[k] * W_w[(64 + k) * 64 + o];
        g_b2[o] = s;
    }
}

// ---------------- final projection out = local@W1 + g2@W2 + b2 ----------------
#define FIN_NPB 64
__global__ void __launch_bounds__(256) k_final(const float* __restrict__ W_w,
                                               float* __restrict__ out) {
    __shared__ float W1s[4096];
    __shared__ float W2s[4096];
    __shared__ float bs[64];
    __shared__ float ls[4][64];
    __shared__ float gs[4][64];
    int tid = threadIdx.x;
    for (int i = tid; i < 4096; i += 256) {
        W1s[i] = W_w[i];
        W2s[i] = g_W2[i];
    }
    if (tid < 64) bs[tid] = g_b2[tid];
    __syncthreads();

    int node0 = blockIdx.x * FIN_NPB;
    for (int nb = 0; nb < FIN_NPB; nb += 4) {
        __syncthreads();
        {
            int nn = node0 + nb + (tid >> 6);
            int c = tid & 63;
            if (nn < NN) {
                ls[tid >> 6][c] = g_local[(size_t)nn * 64 + c];
                gs[tid >> 6][c] = g_g2[(size_t)nn * 64 + c];
            }
        }
        __syncthreads();
        int nn = node0 + nb + (tid >> 6);
        if (nn < NN) {
            int o = tid & 63;
            float aA = bs[o], aB = 0.f, aC = 0.f, aD = 0.f;
            const float4* lr = (const float4*)ls[tid >> 6];
            const float4* gr = (const float4*)gs[tid >> 6];
#pragma unroll
            for (int kk = 0; kk < 16; kk += 2) {
                float4 lv0 = lr[kk], lv1 = lr[kk + 1];
                float4 gv0 = gr[kk], gv1 = gr[kk + 1];
                aA += lv0.x * W1s[(kk * 4 + 0) * 64 + o];
                aA += lv0.y * W1s[(kk * 4 + 1) * 64 + o];
                aA += lv0.z * W1s[(kk * 4 + 2) * 64 + o];
                aA += lv0.w * W1s[(kk * 4 + 3) * 64 + o];
                aB += lv1.x * W1s[(kk * 4 + 4) * 64 + o];
                aB += lv1.y * W1s[(kk * 4 + 5) * 64 + o];
                aB += lv1.z * W1s[(kk * 4 + 6) * 64 + o];
                aB += lv1.w * W1s[(kk * 4 + 7) * 64 + o];
                aC += gv0.x * W2s[(kk * 4 + 0) * 64 + o];
                aC += gv0.y * W2s[(kk * 4 + 1) * 64 + o];
                aC += gv0.z * W2s[(kk * 4 + 2) * 64 + o];
                aC += gv0.w * W2s[(kk * 4 + 3) * 64 + o];
                aD += gv1.x * W2s[(kk * 4 + 4) * 64 + o];
                aD += gv1.y * W2s[(kk * 4 + 5) * 64 + o];
                aD += gv1.z * W2s[(kk * 4 + 6) * 64 + o];
                aD += gv1.w * W2s[(kk * 4 + 7) * 64 + o];
            }
            out[(size_t)nn * 64 + o] = (aA + aB) + (aC + aD);
        }
    }
}

// ---------------- launch ----------------
extern "C" void kernel_launch(void* const* d_in, const int* in_sizes, int n_in,
                              void* d_out, int out_size) {
    const float* x     = (const float*)d_in[0];
    const void*  ei    = d_in[1];
    const float* W_att = (const float*)d_in[2];
    const float* a_src = (const float*)d_in[3];
    const float* a_dst = (const float*)d_in[4];
    const float* W_g   = (const float*)d_in[5];
    const float* b_g   = (const float*)d_in[6];
    const float* W_w   = (const float*)d_in[7];
    const float* b_w   = (const float*)d_in[8];
    float* out = (float*)d_out;

    const int FEAT_SMEM = (64 * ASTRIDE + 64 * 256) * 4;   // 82944 B
    cudaFuncSetAttribute(k_feat, cudaFuncAttributeMaxDynamicSharedMemorySize, FEAT_SMEM);

    // k_feat stays the 4th launch so the profiler slot captures it.
    k_detect<<<1, 256>>>((const unsigned int*)ei);
    k_init<<<256, 256>>>(x);
    k_hist<<<3125, 256>>>(ei);
    k_feat<<<(NN + FEAT_NPB - 1) / FEAT_NPB, 256, FEAT_SMEM>>>(x, W_att);
    k_fold<<<1, 512>>>(W_att, a_src, a_dst);
    k_logit<<<(NN * 32 + 255) / 256, 256>>>(x);
    k_scan_a<<<SCAN_BLKS, 1024>>>();
    k_scan_b<<<1, 128>>>();
    k_scan_c<<<SCAN_BLKS, 1024>>>();
    k_scatter<<<3125, 256>>>(ei);
    k_attn<<<(NN * 32 + 255) / 256, 256>>>();
    k_glob2<<<(NN * 32 + 255) / 256, 256>>>();
    k_wg<<<17, 256>>>(W_g, b_g, W_w, b_w);
    k_final<<<(NN + FIN_NPB - 1) / FIN_NPB, 256>>>(W_w, out);
}

// round 10
// speedup vs baseline: 1.7070x; 1.0730x over previous
#include <cuda_runtime.h>
#include <cuda_fp16.h>

#define NN 100000
#define EE 800000
#define SCAN_BLKS ((NN + 1023) / 1024)   // 98

// ---------------- scratch (__device__ globals: no allocation allowed) ----------------
__device__ __align__(16) __half g_h[(size_t)NN * 256];   // [N][H*64] transformed feats (fp16)
__device__ __align__(16) __half g_xh[(size_t)NN * 64];   // fp16 copy of x
__device__ __align__(16) __half g_g1h[(size_t)NN * 64];  // hop-1 aggregate (fp16)
__device__ __align__(16) __half g_Wh[256 * 64];          // fp16 W_att re-laid: [c=h*64+o][k]
__device__ float g_local[(size_t)NN * 64];   // attention output (head-mean)
__device__ float g_g2[(size_t)NN * 64];      // hop-2 aggregate
__device__ __align__(16) float g_ssrc[NN * 4];           // per-node src logits [N][H]
__device__ __align__(16) float g_sdst[NN * 4];           // per-node dst logits [N][H]
__device__ int   g_deg[NN];
__device__ int   g_offs[NN + 1];
__device__ int   g_cursor[NN];
__device__ int   g_csr[EE];                  // src node per CSR slot (sorted by dst)
__device__ float g_W2[64 * 64];              // W_g @ W_w[64:128]
__device__ float g_b2[64];                   // b_g @ W_w[64:128] + b_w
__device__ float g_V[64 * 8];                // folded logit vectors: V[i][j] (j<4 src, j>=4 dst)
__device__ int   g_is64;                     // edge_index dtype flag
__device__ int   g_bsum[SCAN_BLKS];
__device__ int   g_bbase[SCAN_BLKS];

__device__ __forceinline__ float lrelu(float v) { return v > 0.f ? v : 0.2f * v; }

// ---------------- detect edge_index dtype (int32 vs int64) ----------------
__global__ void k_detect(const unsigned int* __restrict__ w) {
    __shared__ int allzero;
    if (threadIdx.x == 0) allzero = 1;
    __syncthreads();
    for (int i = threadIdx.x; i < 1024; i += blockDim.x)
        if (w[2 * i + 1] != 0u) allzero = 0;
    __syncthreads();
    if (threadIdx.x == 0) g_is64 = allzero;
}

__device__ __forceinline__ int edge_at(const void* ei, int idx) {
    if (g_is64) return (int)((const long long*)ei)[idx];
    return ((const int*)ei)[idx];
}

// ---------------- init: zero degrees + fp16 copy of x ----------------
__global__ void k_init(const float* __restrict__ x) {
    int i = blockIdx.x * blockDim.x + threadIdx.x;
    int st = gridDim.x * blockDim.x;
    for (int j = i; j < NN; j += st) g_deg[j] = 0;
    const float2* x2 = (const float2*)x;
    __half2* xh2 = (__half2*)g_xh;
    for (int j = i; j < NN * 32; j += st) {
        float2 v = x2[j];
        xh2[j] = __floats2half2_rn(v.x, v.y);
    }
}

// ---------------- prep W fp16: g_Wh[c][k] = W_att[h][k][o], c = h*64+o ----------------
__global__ void k_wprep(const float* __restrict__ W_att) {
    int i = blockIdx.x * blockDim.x + threadIdx.x;   // 16384
    if (i < 16384) {
        int c = i >> 6, k = i & 63;
        int h = c >> 6, o = c & 63;
        g_Wh[i] = __float2half_rn(W_att[(size_t)h * 4096 + k * 64 + o]);
    }
}

// ---------------- degree histogram ----------------
__global__ void k_hist(const void* __restrict__ ei) {
    int i = blockIdx.x * blockDim.x + threadIdx.x;
    int st = gridDim.x * blockDim.x;
    for (int e = i; e < EE; e += st) {
        int d = edge_at(ei, EE + e);
        atomicAdd(&g_deg[d], 1);
    }
}

// ---------------- h = x @ W_att via tensor-core mma.m16n8k16 (fp16 in, fp32 acc) ----------------
// Block: 256 thr = 8 warps; block computes 16 nodes x 256 cols. Warp w: cols [w*32, w*32+32).
// B staged in smem with stride 72 halves (bank-conflict-free); A from g_xh (L1-hot).
#define FEAT_NPB 16
__global__ void __launch_bounds__(256) k_feat() {
    __shared__ __half Whs[256 * 72];
    int tid = threadIdx.x;
    // stage W: Whs[c*72 + k] = g_Wh[c*64 + k]
    for (int i = tid; i < 256 * 64; i += 256) {
        int c = i >> 6, k = i & 63;
        Whs[c * 72 + k] = g_Wh[i];
    }
    __syncthreads();

    int w = tid >> 5, lane = tid & 31;
    int g = lane >> 2, tig = lane & 3;
    int nb = blockIdx.x * FEAT_NPB;
    int colb = w * 32;

    float acc[4][4];
#pragma unroll
    for (int s = 0; s < 4; s++)
#pragma unroll
        for (int i = 0; i < 4; i++) acc[s][i] = 0.f;

#pragma unroll
    for (int kc = 0; kc < 4; kc++) {
        int kb = kc * 16;
        // A fragments (row-major m16k16): reg order {rowg/klo, rowg8/klo, rowg/khi, rowg8/khi}
        unsigned int a0 = *(const unsigned int*)&g_xh[(size_t)(nb + g) * 64 + kb + 2 * tig];
        unsigned int a1 = *(const unsigned int*)&g_xh[(size_t)(nb + g + 8) * 64 + kb + 2 * tig];
        unsigned int a2 = *(const unsigned int*)&g_xh[(size_t)(nb + g) * 64 + kb + 8 + 2 * tig];
        unsigned int a3 = *(const unsigned int*)&g_xh[(size_t)(nb + g + 8) * 64 + kb + 8 + 2 * tig];
#pragma unroll
        for (int sub = 0; sub < 4; sub++) {
            int cb = colb + sub * 8;
            // B fragments (col-major k16n8): col = g, k = 2*tig (+8)
            unsigned int b0 = *(const unsigned int*)&Whs[(cb + g) * 72 + kb + 2 * tig];
            unsigned int b1 = *(const unsigned int*)&Whs[(cb + g) * 72 + kb + 8 + 2 * tig];
            asm volatile(
                "mma.sync.aligned.m16n8k16.row.col.f32.f16.f16.f32 "
                "{%0,%1,%2,%3}, {%4,%5,%6,%7}, {%8,%9}, {%0,%1,%2,%3};"
                : "+f"(acc[sub][0]), "+f"(acc[sub][1]), "+f"(acc[sub][2]), "+f"(acc[sub][3])
                : "r"(a0), "r"(a1), "r"(a2), "r"(a3), "r"(b0), "r"(b1));
        }
    }

    // C layout: c0=(row g, col 2tig), c1=(row g, col 2tig+1), c2=(row g+8, col 2tig), c3=(+1)
#pragma unroll
    for (int sub = 0; sub < 4; sub++) {
        int c = colb + sub * 8 + 2 * tig;
        __half2 lo = __floats2half2_rn(acc[sub][0], acc[sub][1]);
        __half2 hi = __floats2half2_rn(acc[sub][2], acc[sub][3]);
        *(unsigned int*)&g_h[(size_t)(nb + g) * 256 + c] = *(unsigned int*)&lo;
        *(unsigned int*)&g_h[(size_t)(nb + g + 8) * 256 + c] = *(unsigned int*)&hi;
    }
}

// ---------------- fold logit vectors: V[i][j] = sum_o W_att[h][i][o]*a[h][o] ----------------
__global__ void k_fold(const float* __restrict__ W_att, const float* __restrict__ a_src,
                       const float* __restrict__ a_dst) {
    int t = threadIdx.x;            // 512 threads: t = i*8 + j
    int i = t >> 3, j = t & 7;
    int h = j & 3;
    const float* a = (j < 4) ? (a_src + h * 64) : (a_dst + h * 64);
    const float* w = W_att + (size_t)h * 4096 + i * 64;
    float s0 = 0.f, s1 = 0.f;
#pragma unroll
    for (int o = 0; o < 64; o += 2) { s0 += w[o] * a[o]; s1 += w[o + 1] * a[o + 1]; }
    g_V[i * 8 + j] = s0 + s1;
}

// ---------------- logits: s[n][j] = x[n] . V[:,j]  (warp per node, no atomics) ----------------
__global__ void __launch_bounds__(256) k_logit(const float* __restrict__ x) {
    __shared__ float Vs[512];
    int tid = threadIdx.x;
    for (int i = tid; i < 512; i += 256) Vs[i] = g_V[i];
    __syncthreads();
    int gw = (blockIdx.x * blockDim.x + tid) >> 5;
    int lane = tid & 31;
    if (gw >= NN) return;
    float2 xv = ((const float2*)(x + (size_t)gw * 64))[lane];
    float p[8];
#pragma unroll
    for (int j = 0; j < 8; j++)
        p[j] = xv.x * Vs[(2 * lane) * 8 + j] + xv.y * Vs[(2 * lane + 1) * 8 + j];
#pragma unroll
    for (int j = 0; j < 8; j++) {
#pragma unroll
        for (int off = 16; off; off >>= 1)
            p[j] += __shfl_xor_sync(0xFFFFFFFFu, p[j], off);
    }
    if (lane == 0) {
        *(float4*)&g_ssrc[gw * 4] = make_float4(p[0], p[1], p[2], p[3]);
        *(float4*)&g_sdst[gw * 4] = make_float4(p[4], p[5], p[6], p[7]);
    }
}

// ---------------- device-wide exclusive scan of g_deg (3 phases) ----------------
__global__ void __launch_bounds__(1024) k_scan_a() {
    __shared__ int sm[1024];
    int tid = threadIdx.x;
    int gid = blockIdx.x * 1024 + tid;
    int v = (gid < NN) ? g_deg[gid] : 0;
    sm[tid] = v;
    __syncthreads();
#pragma unroll
    for (int off = 1; off < 1024; off <<= 1) {
        int t = (tid >= off) ? sm[tid - off] : 0;
        __syncthreads();
        sm[tid] += t;
        __syncthreads();
    }
    if (gid < NN) g_offs[gid] = sm[tid] - v;
    if (tid == 1023) g_bsum[blockIdx.x] = sm[1023];
}

__global__ void __launch_bounds__(128) k_scan_b() {
    __shared__ int sm[128];
    int tid = threadIdx.x;
    int v = (tid < SCAN_BLKS) ? g_bsum[tid] : 0;
    sm[tid] = v;
    __syncthreads();
#pragma unroll
    for (int off = 1; off < 128; off <<= 1) {
        int t = (tid >= off) ? sm[tid - off] : 0;
        __syncthreads();
        sm[tid] += t;
        __syncthreads();
    }
    if (tid < SCAN_BLKS) g_bbase[tid] = sm[tid] - v;
    if (tid == 127) g_offs[NN] = sm[127];
}

__global__ void __launch_bounds__(1024) k_scan_c() {
    int gid = blockIdx.x * 1024 + threadIdx.x;
    if (gid < NN) {
        int o = g_offs[gid] + g_bbase[blockIdx.x];
        g_offs[gid] = o;
        g_cursor[gid] = o;
    }
}

// ---------------- scatter edges into CSR by dst ----------------
__global__ void k_scatter(const void* __restrict__ ei) {
    int i = blockIdx.x * blockDim.x + threadIdx.x;
    int st = gridDim.x * blockDim.x;
    for (int e = i; e < EE; e += st) {
        int s = edge_at(ei, e);
        int d = edge_at(ei, EE + e);
        int pos = atomicAdd(&g_cursor[d], 1);
        g_csr[pos] = s;
    }
}

// ---------------- attention + hop-1, fused, warp per destination node ----------------
__global__ void __launch_bounds__(256) k_attn() {
    __shared__ int   s_src[8][32];
    __shared__ float s_w[8][32][4];
    int wip = threadIdx.x >> 5;
    int gw = (blockIdx.x * blockDim.x + threadIdx.x) >> 5;
    int lane = threadIdx.x & 31;
    if (gw >= NN) return;
    int n = gw;
    int beg = g_offs[n], end = g_offs[n + 1];
    float4 sd = *(const float4*)&g_sdst[n * 4];
    int hsel = lane >> 3;

    float ha[8];
#pragma unroll
    for (int i = 0; i < 8; i++) ha[i] = 0.f;
    float dn0 = 0.f, dn1 = 0.f, dn2 = 0.f, dn3 = 0.f;
    float xa0 = 0.f, xa1 = 0.f;

    for (int c0 = beg; c0 < end; c0 += 32) {
        int lim = min(32, end - c0);
        int j = c0 + lane;
        if (j < end) {
            int s = g_csr[j];
            float4 ss = *(const float4*)&g_ssrc[s * 4];
            float w0 = __expf(lrelu(ss.x + sd.x));
            float w1 = __expf(lrelu(ss.y + sd.y));
            float w2 = __expf(lrelu(ss.z + sd.z));
            float w3 = __expf(lrelu(ss.w + sd.w));
            dn0 += w0; dn1 += w1; dn2 += w2; dn3 += w3;
            s_src[wip][lane] = s;
            s_w[wip][lane][0] = w0;
            s_w[wip][lane][1] = w1;
            s_w[wip][lane][2] = w2;
            s_w[wip][lane][3] = w3;
        }
        __syncwarp();
#pragma unroll 4
        for (int k = 0; k < lim; k++) {
            int   s    = s_src[wip][k];
            float wsel = s_w[wip][k][hsel];
            const uint4* hr = (const uint4*)(g_h + (size_t)s * 256);
            uint4 hv = hr[lane];
            unsigned int xv = ((const unsigned int*)(g_xh + (size_t)s * 64))[lane];
            float2 f0 = __half22float2(*(const __half2*)&hv.x);
            float2 f1 = __half22float2(*(const __half2*)&hv.y);
            float2 f2 = __half22float2(*(const __half2*)&hv.z);
            float2 f3 = __half22float2(*(const __half2*)&hv.w);
            ha[0] += wsel * f0.x; ha[1] += wsel * f0.y;
            ha[2] += wsel * f1.x; ha[3] += wsel * f1.y;
            ha[4] += wsel * f2.x; ha[5] += wsel * f2.y;
            ha[6] += wsel * f3.x; ha[7] += wsel * f3.y;
            float2 xf = __half22float2(*(const __half2*)&xv);
            xa0 += xf.x; xa1 += xf.y;
        }
        __syncwarp();
    }

#pragma unroll
    for (int off = 16; off; off >>= 1) {
        dn0 += __shfl_xor_sync(0xFFFFFFFFu, dn0, off);
        dn1 += __shfl_xor_sync(0xFFFFFFFFu, dn1, off);
        dn2 += __shfl_xor_sync(0xFFFFFFFFu, dn2, off);
        dn3 += __shfl_xor_sync(0xFFFFFFFFu, dn3, off);
    }
    float densel = hsel == 0 ? dn0 : hsel == 1 ? dn1 : hsel == 2 ? dn2 : dn3;
    float isel = 1.f / fmaxf(densel, 1e-16f);

#pragma unroll
    for (int i = 0; i < 8; i++) {
        float v = ha[i] * isel;
        v += __shfl_xor_sync(0xFFFFFFFFu, v, 8);
        v += __shfl_xor_sync(0xFFFFFFFFu, v, 16);
        ha[i] = 0.25f * v;
    }
    if (lane < 8) {
        float4* dst = (float4*)(g_local + (size_t)n * 64 + 8 * lane);
        dst[0] = make_float4(ha[0], ha[1], ha[2], ha[3]);
        dst[1] = make_float4(ha[4], ha[5], ha[6], ha[7]);
    }
    float invd = 1.f / fmaxf((float)(end - beg), 1.f);
    __half2* g1 = (__half2*)(g_g1h + (size_t)n * 64);
    g1[lane] = __floats2half2_rn(xa0 * invd, xa1 * invd);
}

// ---------------- hop-2 (fp16 gather, fp32 out) ----------------
__global__ void __launch_bounds__(256) k_glob2() {
    int gw = (blockIdx.x * blockDim.x + threadIdx.x) >> 5;
    int lane = threadIdx.x & 31;
    if (gw >= NN) return;
    int n = gw;
    int beg = g_offs[n], end = g_offs[n + 1];
    float a0 = 0.f, a1 = 0.f;
#pragma unroll 4
    for (int j = beg; j < end; j++) {
        int s = g_csr[j];
        const unsigned int* r = (const unsigned int*)(g_g1h + (size_t)s * 64);
        unsigned int v = r[lane];
        float2 f = __half22float2(*(const __half2*)&v);
        a0 += f.x; a1 += f.y;
    }
    float inv = 1.f / fmaxf((float)(end - beg), 1.f);
    float2* dst = (float2*)(g_g2 + (size_t)n * 64 + 2 * lane);
    *dst = make_float2(a0 * inv, a1 * inv);
}

// ---------------- fold W_g into W_w lower half ----------------
__global__ void k_wg(const float* __restrict__ W_g, const float* __restrict__ b_g,
                     const float* __restrict__ W_w, const float* __restrict__ b_w) {
    int i0 = blockIdx.x * blockDim.x + threadIdx.x;
    int st = gridDim.x * blockDim.x;
    for (int idx = i0; idx < 4096; idx += st) {
        int i = idx >> 6, o = idx & 63;
        float s = 0.f;
        for (int k = 0; k < 64; k++)
            s += W_g[i * 64 + k] * W_w[(64 + k) * 64 + o];
        g_W2[idx] = s;
    }
    for (int o = i0; o < 64; o += st) {
        float s = b_w[o];
        for (int k = 0; k < 64; k++)
            s += b_g[k] * W_w[(64 + k) * 64 + o];
        g_b2[o] = s;
    }
}

// ---------------- final projection out = local@W1 + g2@W2 + b2 ----------------
#define FIN_NPB 64
__global__ void __launch_bounds__(256) k_final(const float* __restrict__ W_w,
                                               float* __restrict__ out) {
    __shared__ float W1s[4096];
    __shared__ float W2s[4096];
    __shared__ float bs[64];
    __shared__ float ls[4][64];
    __shared__ float gs[4][64];
    int tid = threadIdx.x;
    for (int i = tid; i < 4096; i += 256) {
        W1s[i] = W_w[i];
        W2s[i] = g_W2[i];
    }
    if (tid < 64) bs[tid] = g_b2[tid];
    __syncthreads();

    int node0 = blockIdx.x * FIN_NPB;
    for (int nb = 0; nb < FIN_NPB; nb += 4) {
        __syncthreads();
        {
            int nn = node0 + nb + (tid >> 6);
            int c = tid & 63;
            if (nn < NN) {
                ls[tid >> 6][c] = g_local[(size_t)nn * 64 + c];
                gs[tid >> 6][c] = g_g2[(size_t)nn * 64 + c];
            }
        }
        __syncthreads();
        int nn = node0 + nb + (tid >> 6);
        if (nn < NN) {
            int o = tid & 63;
            float aA = bs[o], aB = 0.f, aC = 0.f, aD = 0.f;
            const float4* lr = (const float4*)ls[tid >> 6];
            const float4* gr = (const float4*)gs[tid >> 6];
#pragma unroll
            for (int kk = 0; kk < 16; kk += 2) {
                float4 lv0 = lr[kk], lv1 = lr[kk + 1];
                float4 gv0 = gr[kk], gv1 = gr[kk + 1];
                aA += lv0.x * W1s[(kk * 4 + 0) * 64 + o];
                aA += lv0.y * W1s[(kk * 4 + 1) * 64 + o];
                aA += lv0.z * W1s[(kk * 4 + 2) * 64 + o];
                aA += lv0.w * W1s[(kk * 4 + 3) * 64 + o];
                aB += lv1.x * W1s[(kk * 4 + 4) * 64 + o];
                aB += lv1.y * W1s[(kk * 4 + 5) * 64 + o];
                aB += lv1.z * W1s[(kk * 4 + 6) * 64 + o];
                aB += lv1.w * W1s[(kk * 4 + 7) * 64 + o];
                aC += gv0.x * W2s[(kk * 4 + 0) * 64 + o];
                aC += gv0.y * W2s[(kk * 4 + 1) * 64 + o];
                aC += gv0.z * W2s[(kk * 4 + 2) * 64 + o];
                aC += gv0.w * W2s[(kk * 4 + 3) * 64 + o];
                aD += gv1.x * W2s[(kk * 4 + 4) * 64 + o];
                aD += gv1.y * W2s[(kk * 4 + 5) * 64 + o];
                aD += gv1.z * W2s[(kk * 4 + 6) * 64 + o];
                aD += gv1.w * W2s[(kk * 4 + 7) * 64 + o];
            }
            out[(size_t)nn * 64 + o] = (aA + aB) + (aC + aD);
        }
    }
}

// ---------------- launch ----------------
extern "C" void kernel_launch(void* const* d_in, const int* in_sizes, int n_in,
                              void* d_out, int out_size) {
    const float* x     = (const float*)d_in[0];
    const void*  ei    = d_in[1];
    const float* W_att = (const float*)d_in[2];
    const float* a_src = (const float*)d_in[3];
    const float* a_dst = (const float*)d_in[4];
    const float* W_g   = (const float*)d_in[5];
    const float* b_g   = (const float*)d_in[6];
    const float* W_w   = (const float*)d_in[7];
    const float* b_w   = (const float*)d_in[8];
    float* out = (float*)d_out;

    // k_feat stays the 4th launch so the profiler slot captures it.
    k_detect<<<1, 256>>>((const unsigned int*)ei);
    k_init<<<256, 256>>>(x);
    k_wprep<<<64, 256>>>(W_att);
    k_feat<<<NN / FEAT_NPB, 256>>>();
    k_hist<<<3125, 256>>>(ei);
    k_fold<<<1, 512>>>(W_att, a_src, a_dst);
    k_logit<<<(NN * 32 + 255) / 256, 256>>>(x);
    k_scan_a<<<SCAN_BLKS, 1024>>>();
    k_scan_b<<<1, 128>>>();
    k_scan_c<<<SCAN_BLKS, 1024>>>();
    k_scatter<<<3125, 256>>>(ei);
    k_attn<<<(NN * 32 + 255) / 256, 256>>>();
    k_glob2<<<(NN * 32 + 255) / 256, 256>>>();
    k_wg<<<17, 256>>>(W_g, b_g, W_w, b_w);
    k_final<<<(NN + FIN_NPB - 1) / FIN_NPB, 256>>>(W_w, out);
}

// round 11
// speedup vs baseline: 1.8275x; 1.0705x over previous
#include <cuda_runtime.h>
#include <cuda_fp16.h>

#define NN 100000
#define EE 800000
#define SCAN_BLKS ((NN + 1023) / 1024)   // 98

// ---------------- scratch (__device__ globals: no allocation allowed) ----------------
__device__ __align__(16) __half g_h[(size_t)NN * 256];   // [N][H*64] transformed feats (fp16)
__device__ __align__(16) __half g_xh[(size_t)NN * 64];   // fp16 copy of x
__device__ __align__(16) __half g_g1h[(size_t)NN * 64];  // hop-1 aggregate (fp16)
__device__ __align__(16) __half g_Wh[256 * 64];          // fp16 W_att re-laid: [c=h*64+o][k]
__device__ float g_local[(size_t)NN * 64];   // attention output (head-mean)
__device__ float g_g2[(size_t)NN * 64];      // hop-2 aggregate
__device__ __align__(16) float g_ssrc[NN * 4];           // per-node src logits [N][H]
__device__ __align__(16) float g_sdst[NN * 4];           // per-node dst logits [N][H]
__device__ int   g_deg[NN];
__device__ int   g_offs[NN + 1];
__device__ int   g_cursor[NN];
__device__ int   g_csr[EE];                  // src node per CSR slot (sorted by dst)
__device__ float g_W2[64 * 64];              // W_g @ W_w[64:128]
__device__ float g_b2[64];                   // b_g @ W_w[64:128] + b_w
__device__ float g_V[64 * 8];                // folded logit vectors: V[i][j] (j<4 src, j>=4 dst)
__device__ int   g_is64;                     // edge_index dtype flag
__device__ int   g_bsum[SCAN_BLKS];
__device__ int   g_bbase[SCAN_BLKS];

__device__ __forceinline__ float lrelu(float v) { return v > 0.f ? v : 0.2f * v; }

// ---------------- detect edge_index dtype (int32 vs int64) ----------------
__global__ void k_detect(const unsigned int* __restrict__ w) {
    __shared__ int allzero;
    if (threadIdx.x == 0) allzero = 1;
    __syncthreads();
    for (int i = threadIdx.x; i < 1024; i += blockDim.x)
        if (w[2 * i + 1] != 0u) allzero = 0;
    __syncthreads();
    if (threadIdx.x == 0) g_is64 = allzero;
}

__device__ __forceinline__ int edge_at(const void* ei, int idx) {
    if (g_is64) return (int)((const long long*)ei)[idx];
    return ((const int*)ei)[idx];
}

// ---------------- init: zero degrees + fp16 copy of x ----------------
__global__ void k_init(const float* __restrict__ x) {
    int i = blockIdx.x * blockDim.x + threadIdx.x;
    int st = gridDim.x * blockDim.x;
    for (int j = i; j < NN; j += st) g_deg[j] = 0;
    const float2* x2 = (const float2*)x;
    __half2* xh2 = (__half2*)g_xh;
    for (int j = i; j < NN * 32; j += st) {
        float2 v = x2[j];
        xh2[j] = __floats2half2_rn(v.x, v.y);
    }
}

// ---------------- prep: fp16 W relayout + folded logit vectors + W2/b2 fold ----------------
__global__ void k_prep(const float* __restrict__ W_att, const float* __restrict__ a_src,
                       const float* __restrict__ a_dst, const float* __restrict__ W_g,
                       const float* __restrict__ b_g, const float* __restrict__ W_w,
                       const float* __restrict__ b_w) {
    int i0 = blockIdx.x * blockDim.x + threadIdx.x;
    int st = gridDim.x * blockDim.x;
    // g_Wh[c][k] = W_att[h][k][o], c = h*64+o
    for (int i = i0; i < 16384; i += st) {
        int c = i >> 6, k = i & 63;
        int h = c >> 6, o = c & 63;
        g_Wh[i] = __float2half_rn(W_att[(size_t)h * 4096 + k * 64 + o]);
    }
    // g_W2 = W_g @ W_w[64:128]
    for (int idx = i0; idx < 4096; idx += st) {
        int i = idx >> 6, o = idx & 63;
        float s = 0.f;
        for (int k = 0; k < 64; k++)
            s += W_g[i * 64 + k] * W_w[(64 + k) * 64 + o];
        g_W2[idx] = s;
    }
    // g_b2 = b_g @ W_w[64:] + b_w
    for (int o = i0; o < 64; o += st) {
        float s = b_w[o];
        for (int k = 0; k < 64; k++)
            s += b_g[k] * W_w[(64 + k) * 64 + o];
        g_b2[o] = s;
    }
    // g_V[i][j] = sum_o W_att[h][i][o] * a[h][o]
    for (int t = i0; t < 512; t += st) {
        int i = t >> 3, j = t & 7;
        int h = j & 3;
        const float* a = (j < 4) ? (a_src + h * 64) : (a_dst + h * 64);
        const float* w = W_att + (size_t)h * 4096 + i * 64;
        float s0 = 0.f, s1 = 0.f;
#pragma unroll
        for (int o = 0; o < 64; o += 2) { s0 += w[o] * a[o]; s1 += w[o + 1] * a[o + 1]; }
        g_V[i * 8 + j] = s0 + s1;
    }
}

// ---------------- degree histogram ----------------
__global__ void k_hist(const void* __restrict__ ei) {
    int i = blockIdx.x * blockDim.x + threadIdx.x;
    int st = gridDim.x * blockDim.x;
    for (int e = i; e < EE; e += st) {
        int d = edge_at(ei, EE + e);
        atomicAdd(&g_deg[d], 1);
    }
}

// ---------------- h = x @ W_att via mma.m16n8k16; 128 nodes/block amortizes W staging ----------------
// Block: 256 thr = 8 warps; warp w owns cols [w*32, w*32+32) over 8 row-tiles of 16 nodes.
#define FEAT_NPB 128
__global__ void __launch_bounds__(256) k_feat() {
    __shared__ __half Whs[256 * 72];
    int tid = threadIdx.x;
    for (int i = tid; i < 256 * 64; i += 256) {
        int c = i >> 6, k = i & 63;
        Whs[c * 72 + k] = g_Wh[i];
    }
    __syncthreads();

    int w = tid >> 5, lane = tid & 31;
    int g = lane >> 2, tig = lane & 3;
    int node0 = blockIdx.x * FEAT_NPB;
    int colb = w * 32;

    // preload B fragments for my strip (8 regs per sub x 4 kc = stays modest: 4 kc x 4 sub x 2)
#pragma unroll 1
    for (int rt = 0; rt < FEAT_NPB / 16; rt++) {
        int nb = node0 + rt * 16;
        if (nb >= NN) break;                     // NN % 16 == 0: full tiles only

        float acc[4][4];
#pragma unroll
        for (int s = 0; s < 4; s++)
#pragma unroll
            for (int i = 0; i < 4; i++) acc[s][i] = 0.f;

#pragma unroll
        for (int kc = 0; kc < 4; kc++) {
            int kb = kc * 16;
            unsigned int a0 = *(const unsigned int*)&g_xh[(size_t)(nb + g) * 64 + kb + 2 * tig];
            unsigned int a1 = *(const unsigned int*)&g_xh[(size_t)(nb + g + 8) * 64 + kb + 2 * tig];
            unsigned int a2 = *(const unsigned int*)&g_xh[(size_t)(nb + g) * 64 + kb + 8 + 2 * tig];
            unsigned int a3 = *(const unsigned int*)&g_xh[(size_t)(nb + g + 8) * 64 + kb + 8 + 2 * tig];
#pragma unroll
            for (int sub = 0; sub < 4; sub++) {
                int cb = colb + sub * 8;
                unsigned int b0 = *(const unsigned int*)&Whs[(cb + g) * 72 + kb + 2 * tig];
                unsigned int b1 = *(const unsigned int*)&Whs[(cb + g) * 72 + kb + 8 + 2 * tig];
                asm volatile(
                    "mma.sync.aligned.m16n8k16.row.col.f32.f16.f16.f32 "
                    "{%0,%1,%2,%3}, {%4,%5,%6,%7}, {%8,%9}, {%0,%1,%2,%3};"
                    : "+f"(acc[sub][0]), "+f"(acc[sub][1]), "+f"(acc[sub][2]), "+f"(acc[sub][3])
                    : "r"(a0), "r"(a1), "r"(a2), "r"(a3), "r"(b0), "r"(b1));
            }
        }

#pragma unroll
        for (int sub = 0; sub < 4; sub++) {
            int c = colb + sub * 8 + 2 * tig;
            __half2 lo = __floats2half2_rn(acc[sub][0], acc[sub][1]);
            __half2 hi = __floats2half2_rn(acc[sub][2], acc[sub][3]);
            *(unsigned int*)&g_h[(size_t)(nb + g) * 256 + c] = *(unsigned int*)&lo;
            *(unsigned int*)&g_h[(size_t)(nb + g + 8) * 256 + c] = *(unsigned int*)&hi;
        }
    }
}

// ---------------- logits: s[n][j] = x[n] . V[:,j]  (warp per node, no atomics) ----------------
__global__ void __launch_bounds__(256) k_logit(const float* __restrict__ x) {
    __shared__ float Vs[512];
    int tid = threadIdx.x;
    for (int i = tid; i < 512; i += 256) Vs[i] = g_V[i];
    __syncthreads();
    int gw = (blockIdx.x * blockDim.x + tid) >> 5;
    int lane = tid & 31;
    if (gw >= NN) return;
    float2 xv = ((const float2*)(x + (size_t)gw * 64))[lane];
    float p[8];
#pragma unroll
    for (int j = 0; j < 8; j++)
        p[j] = xv.x * Vs[(2 * lane) * 8 + j] + xv.y * Vs[(2 * lane + 1) * 8 + j];
#pragma unroll
    for (int j = 0; j < 8; j++) {
#pragma unroll
        for (int off = 16; off; off >>= 1)
            p[j] += __shfl_xor_sync(0xFFFFFFFFu, p[j], off);
    }
    if (lane == 0) {
        *(float4*)&g_ssrc[gw * 4] = make_float4(p[0], p[1], p[2], p[3]);
        *(float4*)&g_sdst[gw * 4] = make_float4(p[4], p[5], p[6], p[7]);
    }
}

// ---------------- device-wide exclusive scan of g_deg (3 phases) ----------------
__global__ void __launch_bounds__(1024) k_scan_a() {
    __shared__ int sm[1024];
    int tid = threadIdx.x;
    int gid = blockIdx.x * 1024 + tid;
    int v = (gid < NN) ? g_deg[gid] : 0;
    sm[tid] = v;
    __syncthreads();
#pragma unroll
    for (int off = 1; off < 1024; off <<= 1) {
        int t = (tid >= off) ? sm[tid - off] : 0;
        __syncthreads();
        sm[tid] += t;
        __syncthreads();
    }
    if (gid < NN) g_offs[gid] = sm[tid] - v;
    if (tid == 1023) g_bsum[blockIdx.x] = sm[1023];
}

__global__ void __launch_bounds__(128) k_scan_b() {
    __shared__ int sm[128];
    int tid = threadIdx.x;
    int v = (tid < SCAN_BLKS) ? g_bsum[tid] : 0;
    sm[tid] = v;
    __syncthreads();
#pragma unroll
    for (int off = 1; off < 128; off <<= 1) {
        int t = (tid >= off) ? sm[tid - off] : 0;
        __syncthreads();
        sm[tid] += t;
        __syncthreads();
    }
    if (tid < SCAN_BLKS) g_bbase[tid] = sm[tid] - v;
    if (tid == 127) g_offs[NN] = sm[127];
}

__global__ void __launch_bounds__(1024) k_scan_c() {
    int gid = blockIdx.x * 1024 + threadIdx.x;
    if (gid < NN) {
        int o = g_offs[gid] + g_bbase[blockIdx.x];
        g_offs[gid] = o;
        g_cursor[gid] = o;
    }
}

// ---------------- scatter edges into CSR by dst ----------------
__global__ void k_scatter(const void* __restrict__ ei) {
    int i = blockIdx.x * blockDim.x + threadIdx.x;
    int st = gridDim.x * blockDim.x;
    for (int e = i; e < EE; e += st) {
        int s = edge_at(ei, e);
        int d = edge_at(ei, EE + e);
        int pos = atomicAdd(&g_cursor[d], 1);
        g_csr[pos] = s;
    }
}

// ---------------- attention + hop-1, fused, warp per destination node ----------------
__global__ void __launch_bounds__(256) k_attn() {
    __shared__ int   s_src[8][32];
    __shared__ float s_w[8][32][4];
    int wip = threadIdx.x >> 5;
    int gw = (blockIdx.x * blockDim.x + threadIdx.x) >> 5;
    int lane = threadIdx.x & 31;
    if (gw >= NN) return;
    int n = gw;
    int beg = g_offs[n], end = g_offs[n + 1];
    float4 sd = *(const float4*)&g_sdst[n * 4];
    int hsel = lane >> 3;

    float ha[8];
#pragma unroll
    for (int i = 0; i < 8; i++) ha[i] = 0.f;
    float dn0 = 0.f, dn1 = 0.f, dn2 = 0.f, dn3 = 0.f;
    float xa0 = 0.f, xa1 = 0.f;

    for (int c0 = beg; c0 < end; c0 += 32) {
        int lim = min(32, end - c0);
        int j = c0 + lane;
        if (j < end) {
            int s = g_csr[j];
            float4 ss = *(const float4*)&g_ssrc[s * 4];
            float w0 = __expf(lrelu(ss.x + sd.x));
            float w1 = __expf(lrelu(ss.y + sd.y));
            float w2 = __expf(lrelu(ss.z + sd.z));
            float w3 = __expf(lrelu(ss.w + sd.w));
            dn0 += w0; dn1 += w1; dn2 += w2; dn3 += w3;
            s_src[wip][lane] = s;
            s_w[wip][lane][0] = w0;
            s_w[wip][lane][1] = w1;
            s_w[wip][lane][2] = w2;
            s_w[wip][lane][3] = w3;
        }
        __syncwarp();
#pragma unroll 4
        for (int k = 0; k < lim; k++) {
            int   s    = s_src[wip][k];
            float wsel = s_w[wip][k][hsel];
            const uint4* hr = (const uint4*)(g_h + (size_t)s * 256);
            uint4 hv = hr[lane];
            unsigned int xv = ((const unsigned int*)(g_xh + (size_t)s * 64))[lane];
            float2 f0 = __half22float2(*(const __half2*)&hv.x);
            float2 f1 = __half22float2(*(const __half2*)&hv.y);
            float2 f2 = __half22float2(*(const __half2*)&hv.z);
            float2 f3 = __half22float2(*(const __half2*)&hv.w);
            ha[0] += wsel * f0.x; ha[1] += wsel * f0.y;
            ha[2] += wsel * f1.x; ha[3] += wsel * f1.y;
            ha[4] += wsel * f2.x; ha[5] += wsel * f2.y;
            ha[6] += wsel * f3.x; ha[7] += wsel * f3.y;
            float2 xf = __half22float2(*(const __half2*)&xv);
            xa0 += xf.x; xa1 += xf.y;
        }
        __syncwarp();
    }

#pragma unroll
    for (int off = 16; off; off >>= 1) {
        dn0 += __shfl_xor_sync(0xFFFFFFFFu, dn0, off);
        dn1 += __shfl_xor_sync(0xFFFFFFFFu, dn1, off);
        dn2 += __shfl_xor_sync(0xFFFFFFFFu, dn2, off);
        dn3 += __shfl_xor_sync(0xFFFFFFFFu, dn3, off);
    }
    float densel = hsel == 0 ? dn0 : hsel == 1 ? dn1 : hsel == 2 ? dn2 : dn3;
    float isel = 1.f / fmaxf(densel, 1e-16f);

#pragma unroll
    for (int i = 0; i < 8; i++) {
        float v = ha[i] * isel;
        v += __shfl_xor_sync(0xFFFFFFFFu, v, 8);
        v += __shfl_xor_sync(0xFFFFFFFFu, v, 16);
        ha[i] = 0.25f * v;
    }
    if (lane < 8) {
        float4* dst = (float4*)(g_local + (size_t)n * 64 + 8 * lane);
        dst[0] = make_float4(ha[0], ha[1], ha[2], ha[3]);
        dst[1] = make_float4(ha[4], ha[5], ha[6], ha[7]);
    }
    float invd = 1.f / fmaxf((float)(end - beg), 1.f);
    __half2* g1 = (__half2*)(g_g1h + (size_t)n * 64);
    g1[lane] = __floats2half2_rn(xa0 * invd, xa1 * invd);
}

// ---------------- hop-2 (fp16 gather, fp32 out) ----------------
__global__ void __launch_bounds__(256) k_glob2() {
    int gw = (blockIdx.x * blockDim.x + threadIdx.x) >> 5;
    int lane = threadIdx.x & 31;
    if (gw >= NN) return;
    int n = gw;
    int beg = g_offs[n], end = g_offs[n + 1];
    float a0 = 0.f, a1 = 0.f;
#pragma unroll 4
    for (int j = beg; j < end; j++) {
        int s = g_csr[j];
        const unsigned int* r = (const unsigned int*)(g_g1h + (size_t)s * 64);
        unsigned int v = r[lane];
        float2 f = __half22float2(*(const __half2*)&v);
        a0 += f.x; a1 += f.y;
    }
    float inv = 1.f / fmaxf((float)(end - beg), 1.f);
    float2* dst = (float2*)(g_g2 + (size_t)n * 64 + 2 * lane);
    *dst = make_float2(a0 * inv, a1 * inv);
}

// ---------------- final projection out = local@W1 + g2@W2 + b2 ----------------
#define FIN_NPB 64
__global__ void __launch_bounds__(256) k_final(const float* __restrict__ W_w,
                                               float* __restrict__ out) {
    __shared__ float W1s[4096];
    __shared__ float W2s[4096];
    __shared__ float bs[64];
    __shared__ float ls[4][64];
    __shared__ float gs[4][64];
    int tid = threadIdx.x;
    for (int i = tid; i < 4096; i += 256) {
        W1s[i] = W_w[i];
        W2s[i] = g_W2[i];
    }
    if (tid < 64) bs[tid] = g_b2[tid];
    __syncthreads();

    int node0 = blockIdx.x * FIN_NPB;
    for (int nb = 0; nb < FIN_NPB; nb += 4) {
        __syncthreads();
        {
            int nn = node0 + nb + (tid >> 6);
            int c = tid & 63;
            if (nn < NN) {
                ls[tid >> 6][c] = g_local[(size_t)nn * 64 + c];
                gs[tid >> 6][c] = g_g2[(size_t)nn * 64 + c];
            }
        }
        __syncthreads();
        int nn = node0 + nb + (tid >> 6);
        if (nn < NN) {
            int o = tid & 63;
            float aA = bs[o], aB = 0.f, aC = 0.f, aD = 0.f;
            const float4* lr = (const float4*)ls[tid >> 6];
            const float4* gr = (const float4*)gs[tid >> 6];
#pragma unroll
            for (int kk = 0; kk < 16; kk += 2) {
                float4 lv0 = lr[kk], lv1 = lr[kk + 1];
                float4 gv0 = gr[kk], gv1 = gr[kk + 1];
                aA += lv0.x * W1s[(kk * 4 + 0) * 64 + o];
                aA += lv0.y * W1s[(kk * 4 + 1) * 64 + o];
                aA += lv0.z * W1s[(kk * 4 + 2) * 64 + o];
                aA += lv0.w * W1s[(kk * 4 + 3) * 64 + o];
                aB += lv1.x * W1s[(kk * 4 + 4) * 64 + o];
                aB += lv1.y * W1s[(kk * 4 + 5) * 64 + o];
                aB += lv1.z * W1s[(kk * 4 + 6) * 64 + o];
                aB += lv1.w * W1s[(kk * 4 + 7) * 64 + o];
                aC += gv0.x * W2s[(kk * 4 + 0) * 64 + o];
                aC += gv0.y * W2s[(kk * 4 + 1) * 64 + o];
                aC += gv0.z * W2s[(kk * 4 + 2) * 64 + o];
                aC += gv0.w * W2s[(kk * 4 + 3) * 64 + o];
                aD += gv1.x * W2s[(kk * 4 + 4) * 64 + o];
                aD += gv1.y * W2s[(kk * 4 + 5) * 64 + o];
                aD += gv1.z * W2s[(kk * 4 + 6) * 64 + o];
                aD += gv1.w * W2s[(kk * 4 + 7) * 64 + o];
            }
            out[(size_t)nn * 64 + o] = (aA + aB) + (aC + aD);
        }
    }
}

// ---------------- launch ----------------
extern "C" void kernel_launch(void* const* d_in, const int* in_sizes, int n_in,
                              void* d_out, int out_size) {
    const float* x     = (const float*)d_in[0];
    const void*  ei    = d_in[1];
    const float* W_att = (const float*)d_in[2];
    const float* a_src = (const float*)d_in[3];
    const float* a_dst = (const float*)d_in[4];
    const float* W_g   = (const float*)d_in[5];
    const float* b_g   = (const float*)d_in[6];
    const float* W_w   = (const float*)d_in[7];
    const float* b_w   = (const float*)d_in[8];
    float* out = (float*)d_out;

    // k_feat stays the 4th launch so the profiler slot captures it.
    k_detect<<<1, 256>>>((const unsigned int*)ei);
    k_init<<<256, 256>>>(x);
    k_prep<<<17, 256>>>(W_att, a_src, a_dst, W_g, b_g, W_w, b_w);
    k_feat<<<(NN + FEAT_NPB - 1) / FEAT_NPB, 256>>>();
    k_hist<<<3125, 256>>>(ei);
    k_logit<<<(NN * 32 + 255) / 256, 256>>>(x);
    k_scan_a<<<SCAN_BLKS, 1024>>>();
    k_scan_b<<<1, 128>>>();
    k_scan_c<<<SCAN_BLKS, 1024>>>();
    k_scatter<<<3125, 256>>>(ei);
    k_attn<<<(NN * 32 + 255) / 256, 256>>>();
    k_glob2<<<(NN * 32 + 255) / 256, 256>>>();
    k_final<<<(NN + FIN_NPB - 1) / FIN_NPB, 256>>>(W_w, out);
}

// round 12
// speedup vs baseline: 1.8363x; 1.0048x over previous
#include <cuda_runtime.h>
#include <cuda_fp16.h>

#define NN 100000
#define EE 800000
#define SCAN_BLKS ((NN + 1023) / 1024)   // 98

// ---------------- scratch (__device__ globals: no allocation allowed) ----------------
__device__ __align__(16) __half g_h[(size_t)NN * 256];   // [N][H*64] transformed feats (fp16)
__device__ __align__(16) __half g_xh[(size_t)NN * 64];   // fp16 copy of x
__device__ __align__(16) __half g_g1h[(size_t)NN * 64];  // hop-1 aggregate (fp16)
__device__ __align__(16) __half g_Wh[256 * 64];          // fp16 W_att re-laid: [c=h*64+o][k]
__device__ float g_local[(size_t)NN * 64];   // attention output (head-mean)
__device__ float g_g2[(size_t)NN * 64];      // hop-2 aggregate
__device__ __align__(16) float g_ssrc[NN * 4];           // per-node src logits [N][H]
__device__ __align__(16) float g_sdst[NN * 4];           // per-node dst logits [N][H]
__device__ int   g_deg[NN];
__device__ int   g_offs[NN + 1];
__device__ int   g_cursor[NN];
__device__ int   g_csr[EE];                  // src node per CSR slot (sorted by dst)
__device__ float g_W2[64 * 64];              // W_g @ W_w[64:128]
__device__ float g_b2[64];                   // b_g @ W_w[64:128] + b_w
__device__ float g_V[64 * 8];                // folded logit vectors: V[i][j] (j<4 src, j>=4 dst)
__device__ int   g_is64;                     // edge_index dtype flag
__device__ int   g_bsum[SCAN_BLKS];
__device__ int   g_bbase[SCAN_BLKS];

__device__ __forceinline__ float lrelu(float v) { return v > 0.f ? v : 0.2f * v; }

// ---------------- detect edge_index dtype (int32 vs int64) ----------------
__global__ void k_detect(const unsigned int* __restrict__ w) {
    __shared__ int allzero;
    if (threadIdx.x == 0) allzero = 1;
    __syncthreads();
    for (int i = threadIdx.x; i < 1024; i += blockDim.x)
        if (w[2 * i + 1] != 0u) allzero = 0;
    __syncthreads();
    if (threadIdx.x == 0) g_is64 = allzero;
}

__device__ __forceinline__ int edge_at(const void* ei, int idx) {
    if (g_is64) return (int)((const long long*)ei)[idx];
    return ((const int*)ei)[idx];
}

// ---------------- init: zero degrees + fp16 copy of x ----------------
__global__ void k_init(const float* __restrict__ x) {
    int i = blockIdx.x * blockDim.x + threadIdx.x;
    int st = gridDim.x * blockDim.x;
    for (int j = i; j < NN; j += st) g_deg[j] = 0;
    const float2* x2 = (const float2*)x;
    __half2* xh2 = (__half2*)g_xh;
    for (int j = i; j < NN * 32; j += st) {
        float2 v = x2[j];
        xh2[j] = __floats2half2_rn(v.x, v.y);
    }
}

// ---------------- prep: fp16 W relayout + folded logit vectors + W2/b2 fold ----------------
__global__ void k_prep(const float* __restrict__ W_att, const float* __restrict__ a_src,
                       const float* __restrict__ a_dst, const float* __restrict__ W_g,
                       const float* __restrict__ b_g, const float* __restrict__ W_w,
                       const float* __restrict__ b_w) {
    int i0 = blockIdx.x * blockDim.x + threadIdx.x;
    int st = gridDim.x * blockDim.x;
    for (int i = i0; i < 16384; i += st) {
        int c = i >> 6, k = i & 63;
        int h = c >> 6, o = c & 63;
        g_Wh[i] = __float2half_rn(W_att[(size_t)h * 4096 + k * 64 + o]);
    }
    for (int idx = i0; idx < 4096; idx += st) {
        int i = idx >> 6, o = idx & 63;
        float s = 0.f;
        for (int k = 0; k < 64; k++)
            s += W_g[i * 64 + k] * W_w[(64 + k) * 64 + o];
        g_W2[idx] = s;
    }
    for (int o = i0; o < 64; o += st) {
        float s = b_w[o];
        for (int k = 0; k < 64; k++)
            s += b_g[k] * W_w[(64 + k) * 64 + o];
        g_b2[o] = s;
    }
    for (int t = i0; t < 512; t += st) {
        int i = t >> 3, j = t & 7;
        int h = j & 3;
        const float* a = (j < 4) ? (a_src + h * 64) : (a_dst + h * 64);
        const float* w = W_att + (size_t)h * 4096 + i * 64;
        float s0 = 0.f, s1 = 0.f;
#pragma unroll
        for (int o = 0; o < 64; o += 2) { s0 += w[o] * a[o]; s1 += w[o + 1] * a[o + 1]; }
        g_V[i * 8 + j] = s0 + s1;
    }
}

// ---------------- degree histogram (in profiler slot this round) ----------------
__global__ void k_hist(const void* __restrict__ ei) {
    int i = blockIdx.x * blockDim.x + threadIdx.x;
    int st = gridDim.x * blockDim.x;
    for (int e = i; e < EE; e += st) {
        int d = edge_at(ei, EE + e);
        atomicAdd(&g_deg[d], 1);
    }
}

// ---------------- h = x @ W_att via mma.m16n8k16; B frags hoisted to registers ----------------
// Block: 256 thr = 8 warps; warp w owns cols [w*32, w*32+32) over 8 row-tiles of 16 nodes.
#define FEAT_NPB 128
__global__ void __launch_bounds__(256) k_feat() {
    __shared__ __half Whs[256 * 72];
    int tid = threadIdx.x;
    for (int i = tid; i < 256 * 64; i += 256) {
        int c = i >> 6, k = i & 63;
        Whs[c * 72 + k] = g_Wh[i];
    }
    __syncthreads();

    int w = tid >> 5, lane = tid & 31;
    int g = lane >> 2, tig = lane & 3;
    int node0 = blockIdx.x * FEAT_NPB;
    int colb = w * 32;

    // hoist ALL B fragments: loop-invariant across row-tiles (32 regs)
    unsigned int bfr[4][4][2];
#pragma unroll
    for (int kc = 0; kc < 4; kc++) {
        int kb = kc * 16;
#pragma unroll
        for (int sub = 0; sub < 4; sub++) {
            int cb = colb + sub * 8;
            bfr[kc][sub][0] = *(const unsigned int*)&Whs[(cb + g) * 72 + kb + 2 * tig];
            bfr[kc][sub][1] = *(const unsigned int*)&Whs[(cb + g) * 72 + kb + 8 + 2 * tig];
        }
    }

#pragma unroll 1
    for (int rt = 0; rt < FEAT_NPB / 16; rt++) {
        int nb = node0 + rt * 16;
        if (nb >= NN) break;                     // NN % 16 == 0: full tiles only

        float acc[4][4];
#pragma unroll
        for (int s = 0; s < 4; s++)
#pragma unroll
            for (int i = 0; i < 4; i++) acc[s][i] = 0.f;

#pragma unroll
        for (int kc = 0; kc < 4; kc++) {
            int kb = kc * 16;
            unsigned int a0 = *(const unsigned int*)&g_xh[(size_t)(nb + g) * 64 + kb + 2 * tig];
            unsigned int a1 = *(const unsigned int*)&g_xh[(size_t)(nb + g + 8) * 64 + kb + 2 * tig];
            unsigned int a2 = *(const unsigned int*)&g_xh[(size_t)(nb + g) * 64 + kb + 8 + 2 * tig];
            unsigned int a3 = *(const unsigned int*)&g_xh[(size_t)(nb + g + 8) * 64 + kb + 8 + 2 * tig];
#pragma unroll
            for (int sub = 0; sub < 4; sub++) {
                asm volatile(
                    "mma.sync.aligned.m16n8k16.row.col.f32.f16.f16.f32 "
                    "{%0,%1,%2,%3}, {%4,%5,%6,%7}, {%8,%9}, {%0,%1,%2,%3};"
                    : "+f"(acc[sub][0]), "+f"(acc[sub][1]), "+f"(acc[sub][2]), "+f"(acc[sub][3])
                    : "r"(a0), "r"(a1), "r"(a2), "r"(a3),
                      "r"(bfr[kc][sub][0]), "r"(bfr[kc][sub][1]));
            }
        }

#pragma unroll
        for (int sub = 0; sub < 4; sub++) {
            int c = colb + sub * 8 + 2 * tig;
            __half2 lo = __floats2half2_rn(acc[sub][0], acc[sub][1]);
            __half2 hi = __floats2half2_rn(acc[sub][2], acc[sub][3]);
            *(unsigned int*)&g_h[(size_t)(nb + g) * 256 + c] = *(unsigned int*)&lo;
            *(unsigned int*)&g_h[(size_t)(nb + g + 8) * 256 + c] = *(unsigned int*)&hi;
        }
    }
}

// ---------------- logits: s[n][j] = x[n] . V[:,j]  (warp per node, no atomics) ----------------
__global__ void __launch_bounds__(256) k_logit(const float* __restrict__ x) {
    __shared__ float Vs[512];
    int tid = threadIdx.x;
    for (int i = tid; i < 512; i += 256) Vs[i] = g_V[i];
    __syncthreads();
    int gw = (blockIdx.x * blockDim.x + tid) >> 5;
    int lane = tid & 31;
    if (gw >= NN) return;
    float2 xv = ((const float2*)(x + (size_t)gw * 64))[lane];
    float p[8];
#pragma unroll
    for (int j = 0; j < 8; j++)
        p[j] = xv.x * Vs[(2 * lane) * 8 + j] + xv.y * Vs[(2 * lane + 1) * 8 + j];
#pragma unroll
    for (int j = 0; j < 8; j++) {
#pragma unroll
        for (int off = 16; off; off >>= 1)
            p[j] += __shfl_xor_sync(0xFFFFFFFFu, p[j], off);
    }
    if (lane == 0) {
        *(float4*)&g_ssrc[gw * 4] = make_float4(p[0], p[1], p[2], p[3]);
        *(float4*)&g_sdst[gw * 4] = make_float4(p[4], p[5], p[6], p[7]);
    }
}

// ---------------- device-wide exclusive scan of g_deg (3 phases) ----------------
__global__ void __launch_bounds__(1024) k_scan_a() {
    __shared__ int sm[1024];
    int tid = threadIdx.x;
    int gid = blockIdx.x * 1024 + tid;
    int v = (gid < NN) ? g_deg[gid] : 0;
    sm[tid] = v;
    __syncthreads();
#pragma unroll
    for (int off = 1; off < 1024; off <<= 1) {
        int t = (tid >= off) ? sm[tid - off] : 0;
        __syncthreads();
        sm[tid] += t;
        __syncthreads();
    }
    if (gid < NN) g_offs[gid] = sm[tid] - v;
    if (tid == 1023) g_bsum[blockIdx.x] = sm[1023];
}

__global__ void __launch_bounds__(128) k_scan_b() {
    __shared__ int sm[128];
    int tid = threadIdx.x;
    int v = (tid < SCAN_BLKS) ? g_bsum[tid] : 0;
    sm[tid] = v;
    __syncthreads();
#pragma unroll
    for (int off = 1; off < 128; off <<= 1) {
        int t = (tid >= off) ? sm[tid - off] : 0;
        __syncthreads();
        sm[tid] += t;
        __syncthreads();
    }
    if (tid < SCAN_BLKS) g_bbase[tid] = sm[tid] - v;
    if (tid == 127) g_offs[NN] = sm[127];
}

__global__ void __launch_bounds__(1024) k_scan_c() {
    int gid = blockIdx.x * 1024 + threadIdx.x;
    if (gid < NN) {
        int o = g_offs[gid] + g_bbase[blockIdx.x];
        g_offs[gid] = o;
        g_cursor[gid] = o;
    }
}

// ---------------- scatter edges into CSR by dst ----------------
__global__ void k_scatter(const void* __restrict__ ei) {
    int i = blockIdx.x * blockDim.x + threadIdx.x;
    int st = gridDim.x * blockDim.x;
    for (int e = i; e < EE; e += st) {
        int s = edge_at(ei, e);
        int d = edge_at(ei, EE + e);
        int pos = atomicAdd(&g_cursor[d], 1);
        g_csr[pos] = s;
    }
}

// ---------------- attention + hop-1, fused, warp per destination node ----------------
__global__ void __launch_bounds__(256) k_attn() {
    __shared__ int   s_src[8][32];
    __shared__ float s_w[8][32][4];
    int wip = threadIdx.x >> 5;
    int gw = (blockIdx.x * blockDim.x + threadIdx.x) >> 5;
    int lane = threadIdx.x & 31;
    if (gw >= NN) return;
    int n = gw;
    int beg = g_offs[n], end = g_offs[n + 1];
    float4 sd = *(const float4*)&g_sdst[n * 4];
    int hsel = lane >> 3;

    float ha[8];
#pragma unroll
    for (int i = 0; i < 8; i++) ha[i] = 0.f;
    float dn0 = 0.f, dn1 = 0.f, dn2 = 0.f, dn3 = 0.f;
    float xa0 = 0.f, xa1 = 0.f;

    for (int c0 = beg; c0 < end; c0 += 32) {
        int lim = min(32, end - c0);
        int j = c0 + lane;
        if (j < end) {
            int s = g_csr[j];
            float4 ss = *(const float4*)&g_ssrc[s * 4];
            float w0 = __expf(lrelu(ss.x + sd.x));
            float w1 = __expf(lrelu(ss.y + sd.y));
            float w2 = __expf(lrelu(ss.z + sd.z));
            float w3 = __expf(lrelu(ss.w + sd.w));
            dn0 += w0; dn1 += w1; dn2 += w2; dn3 += w3;
            s_src[wip][lane] = s;
            s_w[wip][lane][0] = w0;
            s_w[wip][lane][1] = w1;
            s_w[wip][lane][2] = w2;
            s_w[wip][lane][3] = w3;
        }
        __syncwarp();
#pragma unroll 4
        for (int k = 0; k < lim; k++) {
            int   s    = s_src[wip][k];
            float wsel = s_w[wip][k][hsel];
            const uint4* hr = (const uint4*)(g_h + (size_t)s * 256);
            uint4 hv = hr[lane];
            unsigned int xv = ((const unsigned int*)(g_xh + (size_t)s * 64))[lane];
            float2 f0 = __half22float2(*(const __half2*)&hv.x);
            float2 f1 = __half22float2(*(const __half2*)&hv.y);
            float2 f2 = __half22float2(*(const __half2*)&hv.z);
            float2 f3 = __half22float2(*(const __half2*)&hv.w);
            ha[0] += wsel * f0.x; ha[1] += wsel * f0.y;
            ha[2] += wsel * f1.x; ha[3] += wsel * f1.y;
            ha[4] += wsel * f2.x; ha[5] += wsel * f2.y;
            ha[6] += wsel * f3.x; ha[7] += wsel * f3.y;
            float2 xf = __half22float2(*(const __half2*)&xv);
            xa0 += xf.x; xa1 += xf.y;
        }
        __syncwarp();
    }

#pragma unroll
    for (int off = 16; off; off >>= 1) {
        dn0 += __shfl_xor_sync(0xFFFFFFFFu, dn0, off);
        dn1 += __shfl_xor_sync(0xFFFFFFFFu, dn1, off);
        dn2 += __shfl_xor_sync(0xFFFFFFFFu, dn2, off);
        dn3 += __shfl_xor_sync(0xFFFFFFFFu, dn3, off);
    }
    float densel = hsel == 0 ? dn0 : hsel == 1 ? dn1 : hsel == 2 ? dn2 : dn3;
    float isel = 1.f / fmaxf(densel, 1e-16f);

#pragma unroll
    for (int i = 0; i < 8; i++) {
        float v = ha[i] * isel;
        v += __shfl_xor_sync(0xFFFFFFFFu, v, 8);
        v += __shfl_xor_sync(0xFFFFFFFFu, v, 16);
        ha[i] = 0.25f * v;
    }
    if (lane < 8) {
        float4* dst = (float4*)(g_local + (size_t)n * 64 + 8 * lane);
        dst[0] = make_float4(ha[0], ha[1], ha[2], ha[3]);
        dst[1] = make_float4(ha[4], ha[5], ha[6], ha[7]);
    }
    float invd = 1.f / fmaxf((float)(end - beg), 1.f);
    __half2* g1 = (__half2*)(g_g1h + (size_t)n * 64);
    g1[lane] = __floats2half2_rn(xa0 * invd, xa1 * invd);
}

// ---------------- hop-2 (fp16 gather, fp32 out) ----------------
__global__ void __launch_bounds__(256) k_glob2() {
    int gw = (blockIdx.x * blockDim.x + threadIdx.x) >> 5;
    int lane = threadIdx.x & 31;
    if (gw >= NN) return;
    int n = gw;
    int beg = g_offs[n], end = g_offs[n + 1];
    float a0 = 0.f, a1 = 0.f;
#pragma unroll 4
    for (int j = beg; j < end; j++) {
        int s = g_csr[j];
        const unsigned int* r = (const unsigned int*)(g_g1h + (size_t)s * 64);
        unsigned int v = r[lane];
        float2 f = __half22float2(*(const __half2*)&v);
        a0 += f.x; a1 += f.y;
    }
    float inv = 1.f / fmaxf((float)(end - beg), 1.f);
    float2* dst = (float2*)(g_g2 + (size_t)n * 64 + 2 * lane);
    *dst = make_float2(a0 * inv, a1 * inv);
}

// ---------------- final projection out = local@W1 + g2@W2 + b2 ----------------
#define FIN_NPB 64
__global__ void __launch_bounds__(256) k_final(const float* __restrict__ W_w,
                                               float* __restrict__ out) {
    __shared__ float W1s[4096];
    __shared__ float W2s[4096];
    __shared__ float bs[64];
    __shared__ float ls[4][64];
    __shared__ float gs[4][64];
    int tid = threadIdx.x;
    for (int i = tid; i < 4096; i += 256) {
        W1s[i] = W_w[i];
        W2s[i] = g_W2[i];
    }
    if (tid < 64) bs[tid] = g_b2[tid];
    __syncthreads();

    int node0 = blockIdx.x * FIN_NPB;
    for (int nb = 0; nb < FIN_NPB; nb += 4) {
        __syncthreads();
        {
            int nn = node0 + nb + (tid >> 6);
            int c = tid & 63;
            if (nn < NN) {
                ls[tid >> 6][c] = g_local[(size_t)nn * 64 + c];
                gs[tid >> 6][c] = g_g2[(size_t)nn * 64 + c];
            }
        }
        __syncthreads();
        int nn = node0 + nb + (tid >> 6);
        if (nn < NN) {
            int o = tid & 63;
            float aA = bs[o], aB = 0.f, aC = 0.f, aD = 0.f;
            const float4* lr = (const float4*)ls[tid >> 6];
            const float4* gr = (const float4*)gs[tid >> 6];
#pragma unroll
            for (int kk = 0; kk < 16; kk += 2) {
                float4 lv0 = lr[kk], lv1 = lr[kk + 1];
                float4 gv0 = gr[kk], gv1 = gr[kk + 1];
                aA += lv0.x * W1s[(kk * 4 + 0) * 64 + o];
                aA += lv0.y * W1s[(kk * 4 + 1) * 64 + o];
                aA += lv0.z * W1s[(kk * 4 + 2) * 64 + o];
                aA += lv0.w * W1s[(kk * 4 + 3) * 64 + o];
                aB += lv1.x * W1s[(kk * 4 + 4) * 64 + o];
                aB += lv1.y * W1s[(kk * 4 + 5) * 64 + o];
                aB += lv1.z * W1s[(kk * 4 + 6) * 64 + o];
                aB += lv1.w * W1s[(kk * 4 + 7) * 64 + o];
                aC += gv0.x * W2s[(kk * 4 + 0) * 64 + o];
                aC += gv0.y * W2s[(kk * 4 + 1) * 64 + o];
                aC += gv0.z * W2s[(kk * 4 + 2) * 64 + o];
                aC += gv0.w * W2s[(kk * 4 + 3) * 64 + o];
                aD += gv1.x * W2s[(kk * 4 + 4) * 64 + o];
                aD += gv1.y * W2s[(kk * 4 + 5) * 64 + o];
                aD += gv1.z * W2s[(kk * 4 + 6) * 64 + o];
                aD += gv1.w * W2s[(kk * 4 + 7) * 64 + o];
            }
            out[(size_t)nn * 64 + o] = (aA + aB) + (aC + aD);
        }
    }
}

// ---------------- launch ----------------
extern "C" void kernel_launch(void* const* d_in, const int* in_sizes, int n_in,
                              void* d_out, int out_size) {
    const float* x     = (const float*)d_in[0];
    const void*  ei    = d_in[1];
    const float* W_att = (const float*)d_in[2];
    const float* a_src = (const float*)d_in[3];
    const float* a_dst = (const float*)d_in[4];
    const float* W_g   = (const float*)d_in[5];
    const float* b_g   = (const float*)d_in[6];
    const float* W_w   = (const float*)d_in[7];
    const float* b_w   = (const float*)d_in[8];
    float* out = (float*)d_out;

    // k_hist rotated into the profiler slot (4th launch) this round.
    k_detect<<<1, 256>>>((const unsigned int*)ei);
    k_init<<<256, 256>>>(x);
    k_prep<<<17, 256>>>(W_att, a_src, a_dst, W_g, b_g, W_w, b_w);
    k_hist<<<3125, 256>>>(ei);
    k_feat<<<(NN + FEAT_NPB - 1) / FEAT_NPB, 256>>>();
    k_logit<<<(NN * 32 + 255) / 256, 256>>>(x);
    k_scan_a<<<SCAN_BLKS, 1024>>>();
    k_scan_b<<<1, 128>>>();
    k_scan_c<<<SCAN_BLKS, 1024>>>();
    k_scatter<<<3125, 256>>>(ei);
    k_attn<<<(NN * 32 + 255) / 256, 256>>>();
    k_glob2<<<(NN * 32 + 255) / 256, 256>>>();
    k_final<<<(NN + FIN_NPB - 1) / FIN_NPB, 256>>>(W_w, out);
}

// round 13
// speedup vs baseline: 2.1506x; 1.1712x over previous
#include <cuda_runtime.h>
#include <cuda_fp16.h>

#define NN 100000
#define EE 800000
#define SCAN_BLKS ((NN + 1023) / 1024)   // 98

// ---------------- scratch (__device__ globals: no allocation allowed) ----------------
__device__ __align__(16) __half g_h[(size_t)NN * 256];   // [N][H*64] transformed feats (fp16)
__device__ __align__(16) __half g_xh[(size_t)NN * 64];   // fp16 copy of x
__device__ __align__(16) __half g_g1h[(size_t)NN * 64];  // hop-1 aggregate (fp16)
__device__ __align__(16) __half g_Wh[256 * 64];          // fp16 W_att re-laid: [c=h*64+o][k]
__device__ float g_local[(size_t)NN * 64];   // attention output (head-mean)
__device__ float g_g2[(size_t)NN * 64];      // hop-2 aggregate
__device__ __align__(16) float g_ssrc[NN * 4];           // per-node src logits [N][H]
__device__ __align__(16) float g_sdst[NN * 4];           // per-node dst logits [N][H]
__device__ int   g_deg[NN];
__device__ int   g_offs[NN + 1];
__device__ int   g_cursor[NN];
__device__ int   g_csr[EE];                  // src node per CSR slot (sorted by dst)
__device__ float g_W2[64 * 64];              // W_g @ W_w[64:128]
__device__ float g_b2[64];                   // b_g @ W_w[64:128] + b_w
__device__ float g_V[64 * 8];                // folded logit vectors: V[i][j] (j<4 src, j>=4 dst)
__device__ int   g_is64;                     // edge_index dtype flag
__device__ int   g_bsum[SCAN_BLKS];
__device__ int   g_bbase[SCAN_BLKS];

__device__ __forceinline__ float lrelu(float v) { return v > 0.f ? v : 0.2f * v; }

// ---------------- detect edge_index dtype (int32 vs int64) ----------------
__global__ void k_detect(const unsigned int* __restrict__ w) {
    __shared__ int allzero;
    if (threadIdx.x == 0) allzero = 1;
    __syncthreads();
    for (int i = threadIdx.x; i < 1024; i += blockDim.x)
        if (w[2 * i + 1] != 0u) allzero = 0;
    __syncthreads();
    if (threadIdx.x == 0) g_is64 = allzero;
}

__device__ __forceinline__ int edge_at(const void* ei, int idx) {
    if (g_is64) return (int)((const long long*)ei)[idx];
    return ((const int*)ei)[idx];
}

// ---------------- init: zero degrees + fp16 copy of x ----------------
__global__ void k_init(const float* __restrict__ x) {
    int i = blockIdx.x * blockDim.x + threadIdx.x;
    int st = gridDim.x * blockDim.x;
    for (int j = i; j < NN; j += st) g_deg[j] = 0;
    const float2* x2 = (const float2*)x;
    __half2* xh2 = (__half2*)g_xh;
    for (int j = i; j < NN * 32; j += st) {
        float2 v = x2[j];
        xh2[j] = __floats2half2_rn(v.x, v.y);
    }
}

// ---------------- prep: fp16 W relayout + folded logit vectors + W2/b2 fold ----------------
__global__ void k_prep(const float* __restrict__ W_att, const float* __restrict__ a_src,
                       const float* __restrict__ a_dst, const float* __restrict__ W_g,
                       const float* __restrict__ b_g, const float* __restrict__ W_w,
                       const float* __restrict__ b_w) {
    int i0 = blockIdx.x * blockDim.x + threadIdx.x;
    int st = gridDim.x * blockDim.x;
    for (int i = i0; i < 16384; i += st) {
        int c = i >> 6, k = i & 63;
        int h = c >> 6, o = c & 63;
        g_Wh[i] = __float2half_rn(W_att[(size_t)h * 4096 + k * 64 + o]);
    }
    for (int idx = i0; idx < 4096; idx += st) {
        int i = idx >> 6, o = idx & 63;
        float s = 0.f;
        for (int k = 0; k < 64; k++)
            s += W_g[i * 64 + k] * W_w[(64 + k) * 64 + o];
        g_W2[idx] = s;
    }
    for (int o = i0; o < 64; o += st) {
        float s = b_w[o];
        for (int k = 0; k < 64; k++)
            s += b_g[k] * W_w[(64 + k) * 64 + o];
        g_b2[o] = s;
    }
    for (int t = i0; t < 512; t += st) {
        int i = t >> 3, j = t & 7;
        int h = j & 3;
        const float* a = (j < 4) ? (a_src + h * 64) : (a_dst + h * 64);
        const float* w = W_att + (size_t)h * 4096 + i * 64;
        float s0 = 0.f, s1 = 0.f;
#pragma unroll
        for (int o = 0; o < 64; o += 2) { s0 += w[o] * a[o]; s1 += w[o + 1] * a[o + 1]; }
        g_V[i * 8 + j] = s0 + s1;
    }
}

// ---------------- degree histogram ----------------
__global__ void k_hist(const void* __restrict__ ei) {
    int i = blockIdx.x * blockDim.x + threadIdx.x;
    int st = gridDim.x * blockDim.x;
    for (int e = i; e < EE; e += st) {
        int d = edge_at(ei, EE + e);
        atomicAdd(&g_deg[d], 1);
    }
}

// ---------------- h = x @ W_att via mma.m16n8k16 ----------------
#define FEAT_NPB 128
__global__ void __launch_bounds__(256) k_feat() {
    __shared__ __half Whs[256 * 72];
    int tid = threadIdx.x;
    for (int i = tid; i < 256 * 64; i += 256) {
        int c = i >> 6, k = i & 63;
        Whs[c * 72 + k] = g_Wh[i];
    }
    __syncthreads();

    int w = tid >> 5, lane = tid & 31;
    int g = lane >> 2, tig = lane & 3;
    int node0 = blockIdx.x * FEAT_NPB;
    int colb = w * 32;

    unsigned int bfr[4][4][2];
#pragma unroll
    for (int kc = 0; kc < 4; kc++) {
        int kb = kc * 16;
#pragma unroll
        for (int sub = 0; sub < 4; sub++) {
            int cb = colb + sub * 8;
            bfr[kc][sub][0] = *(const unsigned int*)&Whs[(cb + g) * 72 + kb + 2 * tig];
            bfr[kc][sub][1] = *(const unsigned int*)&Whs[(cb + g) * 72 + kb + 8 + 2 * tig];
        }
    }

#pragma unroll 1
    for (int rt = 0; rt < FEAT_NPB / 16; rt++) {
        int nb = node0 + rt * 16;
        if (nb >= NN) break;

        float acc[4][4];
#pragma unroll
        for (int s = 0; s < 4; s++)
#pragma unroll
            for (int i = 0; i < 4; i++) acc[s][i] = 0.f;

#pragma unroll
        for (int kc = 0; kc < 4; kc++) {
            int kb = kc * 16;
            unsigned int a0 = *(const unsigned int*)&g_xh[(size_t)(nb + g) * 64 + kb + 2 * tig];
            unsigned int a1 = *(const unsigned int*)&g_xh[(size_t)(nb + g + 8) * 64 + kb + 2 * tig];
            unsigned int a2 = *(const unsigned int*)&g_xh[(size_t)(nb + g) * 64 + kb + 8 + 2 * tig];
            unsigned int a3 = *(const unsigned int*)&g_xh[(size_t)(nb + g + 8) * 64 + kb + 8 + 2 * tig];
#pragma unroll
            for (int sub = 0; sub < 4; sub++) {
                asm volatile(
                    "mma.sync.aligned.m16n8k16.row.col.f32.f16.f16.f32 "
                    "{%0,%1,%2,%3}, {%4,%5,%6,%7}, {%8,%9}, {%0,%1,%2,%3};"
                    : "+f"(acc[sub][0]), "+f"(acc[sub][1]), "+f"(acc[sub][2]), "+f"(acc[sub][3])
                    : "r"(a0), "r"(a1), "r"(a2), "r"(a3),
                      "r"(bfr[kc][sub][0]), "r"(bfr[kc][sub][1]));
            }
        }

#pragma unroll
        for (int sub = 0; sub < 4; sub++) {
            int c = colb + sub * 8 + 2 * tig;
            __half2 lo = __floats2half2_rn(acc[sub][0], acc[sub][1]);
            __half2 hi = __floats2half2_rn(acc[sub][2], acc[sub][3]);
            *(unsigned int*)&g_h[(size_t)(nb + g) * 256 + c] = *(unsigned int*)&lo;
            *(unsigned int*)&g_h[(size_t)(nb + g + 8) * 256 + c] = *(unsigned int*)&hi;
        }
    }
}

// ---------------- logits: s[n][j] = x[n] . V[:,j] ----------------
__global__ void __launch_bounds__(256) k_logit(const float* __restrict__ x) {
    __shared__ float Vs[512];
    int tid = threadIdx.x;
    for (int i = tid; i < 512; i += 256) Vs[i] = g_V[i];
    __syncthreads();
    int gw = (blockIdx.x * blockDim.x + tid) >> 5;
    int lane = tid & 31;
    if (gw >= NN) return;
    float2 xv = ((const float2*)(x + (size_t)gw * 64))[lane];
    float p[8];
#pragma unroll
    for (int j = 0; j < 8; j++)
        p[j] = xv.x * Vs[(2 * lane) * 8 + j] + xv.y * Vs[(2 * lane + 1) * 8 + j];
#pragma unroll
    for (int j = 0; j < 8; j++) {
#pragma unroll
        for (int off = 16; off; off >>= 1)
            p[j] += __shfl_xor_sync(0xFFFFFFFFu, p[j], off);
    }
    if (lane == 0) {
        *(float4*)&g_ssrc[gw * 4] = make_float4(p[0], p[1], p[2], p[3]);
        *(float4*)&g_sdst[gw * 4] = make_float4(p[4], p[5], p[6], p[7]);
    }
}

// ---------------- device-wide exclusive scan of g_deg (3 phases) ----------------
__global__ void __launch_bounds__(1024) k_scan_a() {
    __shared__ int sm[1024];
    int tid = threadIdx.x;
    int gid = blockIdx.x * 1024 + tid;
    int v = (gid < NN) ? g_deg[gid] : 0;
    sm[tid] = v;
    __syncthreads();
#pragma unroll
    for (int off = 1; off < 1024; off <<= 1) {
        int t = (tid >= off) ? sm[tid - off] : 0;
        __syncthreads();
        sm[tid] += t;
        __syncthreads();
    }
    if (gid < NN) g_offs[gid] = sm[tid] - v;
    if (tid == 1023) g_bsum[blockIdx.x] = sm[1023];
}

__global__ void __launch_bounds__(128) k_scan_b() {
    __shared__ int sm[128];
    int tid = threadIdx.x;
    int v = (tid < SCAN_BLKS) ? g_bsum[tid] : 0;
    sm[tid] = v;
    __syncthreads();
#pragma unroll
    for (int off = 1; off < 128; off <<= 1) {
        int t = (tid >= off) ? sm[tid - off] : 0;
        __syncthreads();
        sm[tid] += t;
        __syncthreads();
    }
    if (tid < SCAN_BLKS) g_bbase[tid] = sm[tid] - v;
    if (tid == 127) g_offs[NN] = sm[127];
}

__global__ void __launch_bounds__(1024) k_scan_c() {
    int gid = blockIdx.x * 1024 + threadIdx.x;
    if (gid < NN) {
        int o = g_offs[gid] + g_bbase[blockIdx.x];
        g_offs[gid] = o;
        g_cursor[gid] = o;
    }
}

// ---------------- scatter edges into CSR by dst ----------------
__global__ void k_scatter(const void* __restrict__ ei) {
    int i = blockIdx.x * blockDim.x + threadIdx.x;
    int st = gridDim.x * blockDim.x;
    for (int e = i; e < EE; e += st) {
        int s = edge_at(ei, e);
        int d = edge_at(ei, EE + e);
        int pos = atomicAdd(&g_cursor[d], 1);
        g_csr[pos] = s;
    }
}

// ---------------- attention + hop-1, fused; 8-deep load batching for MLP ----------------
__global__ void __launch_bounds__(256) k_attn() {
    __shared__ int   s_src[8][32];
    __shared__ float s_w[8][32][4];
    int wip = threadIdx.x >> 5;
    int gw = (blockIdx.x * blockDim.x + threadIdx.x) >> 5;
    int lane = threadIdx.x & 31;
    if (gw >= NN) return;
    int n = gw;
    int beg = g_offs[n], end = g_offs[n + 1];
    float4 sd = *(const float4*)&g_sdst[n * 4];
    int hsel = lane >> 3;

    float ha[8];
#pragma unroll
    for (int i = 0; i < 8; i++) ha[i] = 0.f;
    float dn0 = 0.f, dn1 = 0.f, dn2 = 0.f, dn3 = 0.f;
    float xa0 = 0.f, xa1 = 0.f;

    for (int c0 = beg; c0 < end; c0 += 32) {
        int lim = min(32, end - c0);
        int j = c0 + lane;
        if (j < end) {
            int s = g_csr[j];
            float4 ss = *(const float4*)&g_ssrc[s * 4];
            float w0 = __expf(lrelu(ss.x + sd.x));
            float w1 = __expf(lrelu(ss.y + sd.y));
            float w2 = __expf(lrelu(ss.z + sd.z));
            float w3 = __expf(lrelu(ss.w + sd.w));
            dn0 += w0; dn1 += w1; dn2 += w2; dn3 += w3;
            s_src[wip][lane] = s;
            s_w[wip][lane][0] = w0;
            s_w[wip][lane][1] = w1;
            s_w[wip][lane][2] = w2;
            s_w[wip][lane][3] = w3;
        }
        __syncwarp();
        // dissemination with 8-deep explicit load batching (MLP >= 8)
        for (int k0 = 0; k0 < lim; k0 += 8) {
            int bl = lim - k0; if (bl > 8) bl = 8;
            uint4 hv[8]; unsigned int xv[8];
#pragma unroll
            for (int t = 0; t < 8; t++) {
                if (t < bl) {
                    int s = s_src[wip][k0 + t];
                    hv[t] = ((const uint4*)(g_h + (size_t)s * 256))[lane];
                    xv[t] = ((const unsigned int*)(g_xh + (size_t)s * 64))[lane];
                }
            }
#pragma unroll
            for (int t = 0; t < 8; t++) {
                if (t < bl) {
                    float wsel = s_w[wip][k0 + t][hsel];
                    float2 f0 = __half22float2(*(const __half2*)&hv[t].x);
                    float2 f1 = __half22float2(*(const __half2*)&hv[t].y);
                    float2 f2 = __half22float2(*(const __half2*)&hv[t].z);
                    float2 f3 = __half22float2(*(const __half2*)&hv[t].w);
                    ha[0] += wsel * f0.x; ha[1] += wsel * f0.y;
                    ha[2] += wsel * f1.x; ha[3] += wsel * f1.y;
                    ha[4] += wsel * f2.x; ha[5] += wsel * f2.y;
                    ha[6] += wsel * f3.x; ha[7] += wsel * f3.y;
                    float2 xf = __half22float2(*(const __half2*)&xv[t]);
                    xa0 += xf.x; xa1 += xf.y;
                }
            }
        }
        __syncwarp();
    }

#pragma unroll
    for (int off = 16; off; off >>= 1) {
        dn0 += __shfl_xor_sync(0xFFFFFFFFu, dn0, off);
        dn1 += __shfl_xor_sync(0xFFFFFFFFu, dn1, off);
        dn2 += __shfl_xor_sync(0xFFFFFFFFu, dn2, off);
        dn3 += __shfl_xor_sync(0xFFFFFFFFu, dn3, off);
    }
    float densel = hsel == 0 ? dn0 : hsel == 1 ? dn1 : hsel == 2 ? dn2 : dn3;
    float isel = 1.f / fmaxf(densel, 1e-16f);

#pragma unroll
    for (int i = 0; i < 8; i++) {
        float v = ha[i] * isel;
        v += __shfl_xor_sync(0xFFFFFFFFu, v, 8);
        v += __shfl_xor_sync(0xFFFFFFFFu, v, 16);
        ha[i] = 0.25f * v;
    }
    if (lane < 8) {
        float4* dst = (float4*)(g_local + (size_t)n * 64 + 8 * lane);
        dst[0] = make_float4(ha[0], ha[1], ha[2], ha[3]);
        dst[1] = make_float4(ha[4], ha[5], ha[6], ha[7]);
    }
    float invd = 1.f / fmaxf((float)(end - beg), 1.f);
    __half2* g1 = (__half2*)(g_g1h + (size_t)n * 64);
    g1[lane] = __floats2half2_rn(xa0 * invd, xa1 * invd);
}

// ---------------- hop-2 (fp16 gather, fp32 out) ----------------
__global__ void __launch_bounds__(256) k_glob2() {
    int gw = (blockIdx.x * blockDim.x + threadIdx.x) >> 5;
    int lane = threadIdx.x & 31;
    if (gw >= NN) return;
    int n = gw;
    int beg = g_offs[n], end = g_offs[n + 1];
    float a0 = 0.f, a1 = 0.f;
#pragma unroll 4
    for (int j = beg; j < end; j++) {
        int s = g_csr[j];
        const unsigned int* r = (const unsigned int*)(g_g1h + (size_t)s * 64);
        unsigned int v = r[lane];
        float2 f = __half22float2(*(const __half2*)&v);
        a0 += f.x; a1 += f.y;
    }
    float inv = 1.f / fmaxf((float)(end - beg), 1.f);
    float2* dst = (float2*)(g_g2 + (size_t)n * 64 + 2 * lane);
    *dst = make_float2(a0 * inv, a1 * inv);
}

// ---------------- final projection: register-blocked fp32 GEMM (K=128 concat) ----------------
#define FIN_NPB 128
#define FIN_ASTR 132
#define FIN_WSTR 68
__global__ void __launch_bounds__(256) k_final(const float* __restrict__ W_w,
                                               float* __restrict__ out) {
    extern __shared__ float fsm[];
    float* inT = fsm;                      // [128][FIN_ASTR]  k-major inputs, transposed
    float* Ws  = fsm + 128 * FIN_ASTR;     // [128][FIN_WSTR]  stacked [W_w(top);W2]
    float* bs  = Ws + 128 * FIN_WSTR;      // [64]
    int tid = threadIdx.x;
    int node0 = blockIdx.x * FIN_NPB;

    for (int i = tid; i < 128 * 64; i += 256) {
        int k = i >> 6, o = i & 63;
        Ws[k * FIN_WSTR + o] = (k < 64) ? W_w[k * 64 + o] : g_W2[(k - 64) * 64 + o];
    }
    if (tid < 64) bs[tid] = g_b2[tid];
    for (int i = tid; i < 128 * 64; i += 256) {
        int n = i >> 6, k = i & 63;
        int nn = node0 + n;
        float lv = 0.f, gv = 0.f;
        if (nn < NN) {
            lv = g_local[(size_t)nn * 64 + k];
            gv = g_g2[(size_t)nn * 64 + k];
        }
        inT[k * FIN_ASTR + n] = lv;
        inT[(64 + k) * FIN_ASTR + n] = gv;
    }
    __syncthreads();

    int tx = tid & 7, ty = tid >> 3;       // tx: 8-col group, ty: 4-node group
    int c0 = tx * 8, n0 = ty * 4;

    float acc[4][8];
#pragma unroll
    for (int i = 0; i < 4; i++)
#pragma unroll
        for (int jj = 0; jj < 8; jj++) acc[i][jj] = 0.f;

#pragma unroll 4
    for (int k = 0; k < 128; k++) {
        float4 av = *(const float4*)&inT[k * FIN_ASTR + n0];
        float4 b0 = *(const float4*)&Ws[k * FIN_WSTR + c0];
        float4 b1 = *(const float4*)&Ws[k * FIN_WSTR + c0 + 4];
        float avv[4] = {av.x, av.y, av.z, av.w};
        float bvv[8] = {b0.x, b0.y, b0.z, b0.w, b1.x, b1.y, b1.z, b1.w};
#pragma unroll
        for (int i = 0; i < 4; i++)
#pragma unroll
            for (int jj = 0; jj < 8; jj++) acc[i][jj] += avv[i] * bvv[jj];
    }

#pragma unroll
    for (int i = 0; i < 4; i++) {
        int nn = node0 + n0 + i;
        if (nn < NN) {
            float4 o0 = make_float4(acc[i][0] + bs[c0 + 0], acc[i][1] + bs[c0 + 1],
                                    acc[i][2] + bs[c0 + 2], acc[i][3] + bs[c0 + 3]);
            float4 o1 = make_float4(acc[i][4] + bs[c0 + 4], acc[i][5] + bs[c0 + 5],
                                    acc[i][6] + bs[c0 + 6], acc[i][7] + bs[c0 + 7]);
            *(float4*)&out[(size_t)nn * 64 + c0] = o0;
            *(float4*)&out[(size_t)nn * 64 + c0 + 4] = o1;
        }
    }
}

// ---------------- launch ----------------
extern "C" void kernel_launch(void* const* d_in, const int* in_sizes, int n_in,
                              void* d_out, int out_size) {
    const float* x     = (const float*)d_in[0];
    const void*  ei    = d_in[1];
    const float* W_att = (const float*)d_in[2];
    const float* a_src = (const float*)d_in[3];
    const float* a_dst = (const float*)d_in[4];
    const float* W_g   = (const float*)d_in[5];
    const float* b_g   = (const float*)d_in[6];
    const float* W_w   = (const float*)d_in[7];
    const float* b_w   = (const float*)d_in[8];
    float* out = (float*)d_out;

    const int FIN_SMEM = (128 * FIN_ASTR + 128 * FIN_WSTR + 64) * 4;   // 102656 B
    cudaFuncSetAttribute(k_final, cudaFuncAttributeMaxDynamicSharedMemorySize, FIN_SMEM);

    // k_feat back in the profiler slot (4th launch) to check the R12 hoist.
    k_detect<<<1, 256>>>((const unsigned int*)ei);
    k_init<<<256, 256>>>(x);
    k_prep<<<17, 256>>>(W_att, a_src, a_dst, W_g, b_g, W_w, b_w);
    k_feat<<<(NN + FEAT_NPB - 1) / FEAT_NPB, 256>>>();
    k_hist<<<3125, 256>>>(ei);
    k_logit<<<(NN * 32 + 255) / 256, 256>>>(x);
    k_scan_a<<<SCAN_BLKS, 1024>>>();
    k_scan_b<<<1, 128>>>();
    k_scan_c<<<SCAN_BLKS, 1024>>>();
    k_scatter<<<3125, 256>>>(ei);
    k_attn<<<(NN * 32 + 255) / 256, 256>>>();
    k_glob2<<<(NN * 32 + 255) / 256, 256>>>();
    k_final<<<(NN + FIN_NPB - 1) / FIN_NPB, 256, FIN_SMEM>>>(W_w, out);
}